// round 7
// baseline (speedup 1.0000x reference)
#include <cuda_runtime.h>
#include <cuda_bf16.h>
#include <cstdint>
#include <math.h>

#define DIM    1024
#define HEADS  16
#define DH     64
#define BATCH  2
#define QL     1024
#define KL     4096
#define INNER  4096
#define MQ     (BATCH*QL)
#define MKV    (BATCH*KL)
typedef __nv_bfloat16 bf16;

// ---------------- scratch ----------------
#define ALN __align__(256)
__device__ ALN bf16 w_q_h [DIM*DIM],    w_q_l [DIM*DIM];
__device__ ALN bf16 w_kv_h[2*DIM*DIM],  w_kv_l[2*DIM*DIM];
__device__ ALN bf16 w_o_h [DIM*DIM],    w_o_l [DIM*DIM];
__device__ ALN bf16 w_1_h [INNER*DIM],  w_1_l [INNER*DIM];
__device__ ALN bf16 w_2_h [DIM*INNER],  w_2_l [DIM*INNER];
__device__ ALN bf16 g_qln_h [MQ*DIM],   g_qln_l [MQ*DIM];
__device__ ALN bf16 g_kvpe_h[MKV*DIM],  g_kvpe_l[MKV*DIM];
__device__ ALN bf16 g_qp_h  [MQ*DIM],   g_qp_l  [MQ*DIM];
__device__ ALN bf16 g_kvp_h [MKV*2*DIM],g_kvp_l [MKV*2*DIM];
__device__ ALN bf16 g_ctx_h [MQ*DIM],   g_ctx_l [MQ*DIM];
__device__ ALN float g_attn [MQ*DIM];
__device__ ALN bf16 g_hb_h  [MQ*DIM],   g_hb_l  [MQ*DIM];
__device__ ALN bf16 g_in_h  [MQ*INNER], g_in_l  [MQ*INNER];

// ---------------- PTX helpers (sm_80-compatible only) ----------------
__device__ __forceinline__ uint32_t smem_u32(const void* p){ uint32_t a;
  asm("{ .reg .u64 t; cvta.to.shared.u64 t, %1; cvt.u32.u64 %0, t; }":"=r"(a):"l"(p)); return a; }
__device__ __forceinline__ void cp16(uint32_t d, const void* s){
  asm volatile("cp.async.cg.shared.global [%0],[%1],16;"::"r"(d),"l"(s)); }
#define CP_COMMIT() asm volatile("cp.async.commit_group;":::"memory")
#define CP_WAIT0()  asm volatile("cp.async.wait_group 0;":::"memory")
#define CP_WAIT1()  asm volatile("cp.async.wait_group 1;":::"memory")

__device__ __forceinline__ void ldsm4(uint32_t* r, uint32_t a){
  asm volatile("ldmatrix.sync.aligned.m8n8.x4.shared.b16 {%0,%1,%2,%3},[%4];"
    :"=r"(r[0]),"=r"(r[1]),"=r"(r[2]),"=r"(r[3]):"r"(a));
}
__device__ __forceinline__ void ldsm4t(uint32_t* r, uint32_t a){
  asm volatile("ldmatrix.sync.aligned.m8n8.x4.trans.shared.b16 {%0,%1,%2,%3},[%4];"
    :"=r"(r[0]),"=r"(r[1]),"=r"(r[2]),"=r"(r[3]):"r"(a));
}
__device__ __forceinline__ void mma16816(float* d, const uint32_t* a, uint32_t b0, uint32_t b1){
  asm volatile("mma.sync.aligned.m16n8k16.row.col.f32.bf16.bf16.f32 "
    "{%0,%1,%2,%3},{%4,%5,%6,%7},{%8,%9},{%0,%1,%2,%3};"
    :"+f"(d[0]),"+f"(d[1]),"+f"(d[2]),"+f"(d[3])
    :"r"(a[0]),"r"(a[1]),"r"(a[2]),"r"(a[3]),"r"(b0),"r"(b1));
}
__device__ __forceinline__ uint32_t pack2(float a, float b, uint32_t& lo){
  bf16 ha=__float2bfloat16(a), hb=__float2bfloat16(b);
  bf16 la=__float2bfloat16(a-__bfloat162float(ha));
  bf16 lb=__float2bfloat16(b-__bfloat162float(hb));
  lo=(uint32_t)__bfloat16_as_ushort(la)|((uint32_t)__bfloat16_as_ushort(lb)<<16);
  return (uint32_t)__bfloat16_as_ushort(ha)|((uint32_t)__bfloat16_as_ushort(hb)<<16);
}
__device__ __forceinline__ float gelu_tanh(float x){
  return 0.5f*x*(1.0f+tanhf(0.7978845608028654f*(x+0.044715f*x*x*x)));
}
__device__ __forceinline__ uint32_t soff(uint32_t r, uint32_t ch){
  return r*128u + ((ch ^ (r & 7u)) << 4);
}

// ---------------- elementwise ----------------
__global__ void __launch_bounds__(256) ln_split_kernel(const float* __restrict__ x,
    const float* __restrict__ sc_, const float* __restrict__ bi_,
    bf16* __restrict__ oh, bf16* __restrict__ ol){
  const int row=blockIdx.x, t=threadIdx.x;
  const float4 v=((const float4*)(x+(size_t)row*DIM))[t];
  float s=v.x+v.y+v.z+v.w, ss=v.x*v.x+v.y*v.y+v.z*v.z+v.w*v.w;
  #pragma unroll
  for(int o=16;o;o>>=1){ s+=__shfl_xor_sync(~0u,s,o); ss+=__shfl_xor_sync(~0u,ss,o); }
  __shared__ float sm1[8], sm2[8];
  if((t&31)==0){ sm1[t>>5]=s; sm2[t>>5]=ss; }
  __syncthreads();
  float tot=0.f,tot2=0.f;
  #pragma unroll
  for(int i=0;i<8;i++){ tot+=sm1[i]; tot2+=sm2[i]; }
  const float mean=tot*(1.f/DIM), var=tot2*(1.f/DIM)-mean*mean, inv=rsqrtf(var+1e-6f);
  const float4 sc=((const float4*)sc_)[t], bi=((const float4*)bi_)[t];
  float o0=(v.x-mean)*inv*sc.x+bi.x, o1=(v.y-mean)*inv*sc.y+bi.y;
  float o2=(v.z-mean)*inv*sc.z+bi.z, o3=(v.w-mean)*inv*sc.w+bi.w;
  uint32_t l0,l1,h0=pack2(o0,o1,l0),h1=pack2(o2,o3,l1);
  ((uint2*)(oh+(size_t)row*DIM))[t]=make_uint2(h0,h1);
  ((uint2*)(ol+(size_t)row*DIM))[t]=make_uint2(l0,l1);
}

__global__ void __launch_bounds__(256) kvpe_split_kernel(const float* __restrict__ kv,
    const float* __restrict__ pe, const int* __restrict__ ids,
    bf16* __restrict__ oh, bf16* __restrict__ ol){
  const int row=blockIdx.x, t=threadIdx.x;
  const int id=ids[row];
  float4 a=((const float4*)(kv+(size_t)row*DIM))[t];
  const float4 p=((const float4*)(pe+(size_t)id*DIM))[t];
  a.x+=p.x; a.y+=p.y; a.z+=p.z; a.w+=p.w;
  uint32_t l0,l1,h0=pack2(a.x,a.y,l0),h1=pack2(a.z,a.w,l1);
  ((uint2*)(oh+(size_t)row*DIM))[t]=make_uint2(h0,h1);
  ((uint2*)(ol+(size_t)row*DIM))[t]=make_uint2(l0,l1);
}

__global__ void __launch_bounds__(256) tsplit_kernel(const float* __restrict__ W,
    bf16* __restrict__ Th, bf16* __restrict__ Tl, int K, int N){
  __shared__ float t[32][33];
  const int tx=threadIdx.x, ty=threadIdx.y;
  const int bx=blockIdx.x*32, by=blockIdx.y*32;
  #pragma unroll
  for(int yy=ty;yy<32;yy+=8) t[yy][tx]=W[(size_t)(by+yy)*N+bx+tx];
  __syncthreads();
  #pragma unroll
  for(int yy=ty;yy<32;yy+=8){
    float v=t[tx][yy];
    bf16 h=__float2bfloat16(v), l=__float2bfloat16(v-__bfloat162float(h));
    const size_t idx=(size_t)(bx+yy)*K+by+tx;
    Th[idx]=h; Tl[idx]=l;
  }
}

// ---------------- HMMA GEMM: C[M,N] = A[M,K] @ Bt[N,K]^T ----------------
// tile 128x256x64; stage (96KB): Ah@0, Al@16384, Bh@32768 (32KB), Bl@65536 (32KB)
#define MM_STAGE 98304
#define MM_SMEM  (2*MM_STAGE)

__device__ __forceinline__ void mm_load(const bf16* Ah,const bf16* Al,const bf16* Bh,const bf16* Bl,
    uint32_t sb,int tid,int row0,int col0,int K,int s){
  const int k0=s*64; const uint32_t st=sb+(s&1)*MM_STAGE;
  #pragma unroll
  for(int i=0;i<4;i++){
    int id=tid+256*i; uint32_t r=id>>3, c=id&7; uint32_t so=soff(r,c);
    cp16(st+so,       Ah+(size_t)(row0+r)*K+k0+c*8);
    cp16(st+16384+so, Al+(size_t)(row0+r)*K+k0+c*8);
  }
  #pragma unroll
  for(int i=0;i<8;i++){
    int id=tid+256*i; uint32_t r=id>>3, c=id&7; uint32_t so=soff(r,c);
    cp16(st+32768+so, Bh+(size_t)(col0+r)*K+k0+c*8);
    cp16(st+65536+so, Bl+(size_t)(col0+r)*K+k0+c*8);
  }
}

// EPI: 0=split-bf16, 1=+residual fp32, 2=gelu split-bf16, 3=scale 0.125 split-bf16
template <int EPI>
__global__ void __launch_bounds__(256,1) mm_kernel(const bf16* __restrict__ Ah,const bf16* __restrict__ Al,
    const bf16* __restrict__ Bh,const bf16* __restrict__ Bl,
    const float* __restrict__ R, float* __restrict__ Cf,
    bf16* __restrict__ Ch, bf16* __restrict__ Cl, int N, int K){
  extern __shared__ char smc[];
  const uint32_t sb=smem_u32(smc);
  const int tid=threadIdx.x, wid=tid>>5, lane=tid&31;
  const int row0=blockIdx.y*128, col0=blockIdx.x*256;
  const int m0=(wid>>2)*64, n0=(wid&3)*64;

  float acc[4][8][4];
  #pragma unroll
  for(int i=0;i<4;i++)
    #pragma unroll
    for(int j=0;j<8;j++)
      #pragma unroll
      for(int k=0;k<4;k++) acc[i][j][k]=0.f;

  const int S=K/64;
  mm_load(Ah,Al,Bh,Bl,sb,tid,row0,col0,K,0); CP_COMMIT();
  if(S>1){ mm_load(Ah,Al,Bh,Bl,sb,tid,row0,col0,K,1); CP_COMMIT(); }

  for(int s=0;s<S;s++){
    if(s+1<S) CP_WAIT1(); else CP_WAIT0();
    __syncthreads();
    const uint32_t st=sb+(s&1)*MM_STAGE;
    #pragma unroll
    for(int kk=0;kk<4;kk++){
      const uint32_t chk=kk*2+(lane>>4);
      uint32_t bh[4][4], bl[4][4];
      #pragma unroll
      for(int ni=0;ni<4;ni++){
        const uint32_t r=n0+ni*16+(lane&15);
        const uint32_t o=soff(r,chk);
        ldsm4(bh[ni], st+32768+o);
        ldsm4(bl[ni], st+65536+o);
      }
      #pragma unroll
      for(int mi=0;mi<4;mi++){
        const uint32_t r=m0+mi*16+(lane&15);
        const uint32_t o=soff(r,chk);
        uint32_t ah[4], al[4];
        ldsm4(ah, st+o);
        ldsm4(al, st+16384+o);
        #pragma unroll
        for(int nj=0;nj<8;nj++){
          const uint32_t b0h=bh[nj>>1][nj&1], b1h=bh[nj>>1][(nj&1)+2];
          const uint32_t b0l=bl[nj>>1][nj&1], b1l=bl[nj>>1][(nj&1)+2];
          mma16816(acc[mi][nj], ah, b0h, b1h);
          mma16816(acc[mi][nj], ah, b0l, b1l);
          mma16816(acc[mi][nj], al, b0h, b1h);
        }
      }
    }
    __syncthreads();
    if(s+2<S){ mm_load(Ah,Al,Bh,Bl,sb,tid,row0,col0,K,s+2); CP_COMMIT(); }
  }

  #pragma unroll
  for(int mi=0;mi<4;mi++){
    #pragma unroll
    for(int h=0;h<2;h++){
      const int grow=row0+m0+mi*16+(lane>>2)+h*8;
      #pragma unroll
      for(int nj=0;nj<8;nj++){
        const int gcol=col0+n0+nj*8+2*(lane&3);
        const float v0=acc[mi][nj][2*h], v1=acc[mi][nj][2*h+1];
        if(EPI==1){
          float2 rv=*(const float2*)(R+(size_t)grow*N+gcol);
          *(float2*)(Cf+(size_t)grow*N+gcol)=make_float2(v0+rv.x, v1+rv.y);
        } else {
          float a=v0,b=v1;
          if(EPI==2){ a=gelu_tanh(a); b=gelu_tanh(b); }
          if(EPI==3){ a*=0.125f; b*=0.125f; }
          uint32_t lo, hi=pack2(a,b,lo);
          *(uint32_t*)(Ch+(size_t)grow*N+gcol)=hi;
          *(uint32_t*)(Cl+(size_t)grow*N+gcol)=lo;
        }
      }
    }
  }
}

// ---------------- FA2 attention (HMMA), 256 threads, 2 CTAs/SM ----------------
// smem: QH @0 (16KB), QL @16384; stage buf @32768+buf*32768: KH+0, KL+8192, VH+16384, VL+24576
#define AT_SMEM 98304

__device__ __forceinline__ void attn_loadkv(const bf16* KVh,const bf16* KVl,
    uint32_t sb,int tid,size_t kr0,int h,int buf){
  const uint32_t st=sb+32768+buf*32768;
  #pragma unroll
  for(int i=0;i<2;i++){
    int id=tid+256*i; uint32_t r=id>>3, c=id&7; uint32_t so=soff(r,c);
    const size_t g=(kr0+r)*2048 + (size_t)h*64 + c*8;
    cp16(st+so,        KVh+g);
    cp16(st+8192+so,   KVl+g);
    cp16(st+16384+so,  KVh+g+1024);
    cp16(st+24576+so,  KVl+g+1024);
  }
}

__global__ void __launch_bounds__(256,2) attn_kernel(const bf16* __restrict__ Qh,const bf16* __restrict__ Ql,
    const bf16* __restrict__ KVh,const bf16* __restrict__ KVl,
    bf16* __restrict__ Ch, bf16* __restrict__ Cl){
  extern __shared__ char smc[];
  const uint32_t sb=smem_u32(smc);
  const int tid=threadIdx.x, wid=tid>>5, lane=tid&31;
  const int qt=blockIdx.x, h=blockIdx.y, b=blockIdx.z;
  const size_t qrow0=(size_t)(b*QL+qt*128);

  #pragma unroll
  for(int i=0;i<4;i++){
    int id=tid+256*i; uint32_t r=id>>3, c=id&7; uint32_t so=soff(r,c);
    const size_t g=(qrow0+r)*DIM + (size_t)h*64 + c*8;
    cp16(sb+so,       Qh+g);
    cp16(sb+16384+so, Ql+g);
  }
  attn_loadkv(KVh,KVl,sb,tid,(size_t)b*KL,h,0); CP_COMMIT();
  attn_loadkv(KVh,KVl,sb,tid,(size_t)b*KL+64,h,1); CP_COMMIT();

  float O[8][4];
  #pragma unroll
  for(int j=0;j<8;j++)
    #pragma unroll
    for(int k=0;k<4;k++) O[j][k]=0.f;
  float mrun[2]={-1e30f,-1e30f}, lrun[2]={0.f,0.f};

  const int NT=KL/64;
  for(int t=0;t<NT;t++){
    if(t+1<NT) CP_WAIT1(); else CP_WAIT0();
    __syncthreads();
    const uint32_t st=sb+32768+(t&1)*32768;

    // ---- S = Q @ K^T (3-split), 16 q-rows per warp ----
    float S[8][4];
    #pragma unroll
    for(int j=0;j<8;j++)
      #pragma unroll
      for(int k=0;k<4;k++) S[j][k]=0.f;
    #pragma unroll
    for(int kk=0;kk<4;kk++){
      const uint32_t chk=kk*2+(lane>>4);
      uint32_t qh[4], ql[4];
      {
        const uint32_t r=wid*16+(lane&15);
        const uint32_t o=soff(r,chk);
        ldsm4(qh, sb+o);
        ldsm4(ql, sb+16384+o);
      }
      #pragma unroll
      for(int nk=0;nk<4;nk++){
        const uint32_t r=nk*16+(lane&15);
        const uint32_t o=soff(r,chk);
        uint32_t kh[4], kl[4];
        ldsm4(kh, st+o);
        ldsm4(kl, st+8192+o);
        mma16816(S[2*nk],   qh, kh[0], kh[2]);
        mma16816(S[2*nk+1], qh, kh[1], kh[3]);
        mma16816(S[2*nk],   qh, kl[0], kl[2]);
        mma16816(S[2*nk+1], qh, kl[1], kl[3]);
        mma16816(S[2*nk],   ql, kh[0], kh[2]);
        mma16816(S[2*nk+1], ql, kh[1], kh[3]);
      }
    }

    // ---- online softmax (scale already folded into Q) ----
    float alpha[2];
    #pragma unroll
    for(int hh=0;hh<2;hh++){
      float mx=-1e30f;
      #pragma unroll
      for(int nj=0;nj<8;nj++){ mx=fmaxf(mx,S[nj][2*hh]); mx=fmaxf(mx,S[nj][2*hh+1]); }
      mx=fmaxf(mx,__shfl_xor_sync(~0u,mx,1));
      mx=fmaxf(mx,__shfl_xor_sync(~0u,mx,2));
      const float mn=fmaxf(mrun[hh],mx);
      alpha[hh]=__expf(mrun[hh]-mn);
      mrun[hh]=mn;
      float sum=0.f;
      #pragma unroll
      for(int nj=0;nj<8;nj++){
        float e0=__expf(S[nj][2*hh]-mn), e1=__expf(S[nj][2*hh+1]-mn);
        S[nj][2*hh]=e0; S[nj][2*hh+1]=e1; sum+=e0+e1;
      }
      sum+=__shfl_xor_sync(~0u,sum,1);
      sum+=__shfl_xor_sync(~0u,sum,2);
      lrun[hh]=lrun[hh]*alpha[hh]+sum;
      #pragma unroll
      for(int nj=0;nj<8;nj++){ O[nj][2*hh]*=alpha[hh]; O[nj][2*hh+1]*=alpha[hh]; }
    }

    // ---- O += P @ V (3-split), V via ldmatrix.trans ----
    #pragma unroll
    for(int ki=0;ki<4;ki++){
      uint32_t ph[4], pl[4];
      ph[0]=pack2(S[2*ki][0],  S[2*ki][1],  pl[0]);
      ph[1]=pack2(S[2*ki][2],  S[2*ki][3],  pl[1]);
      ph[2]=pack2(S[2*ki+1][0],S[2*ki+1][1],pl[2]);
      ph[3]=pack2(S[2*ki+1][2],S[2*ki+1][3],pl[3]);
      #pragma unroll
      for(int nd=0;nd<4;nd++){
        const uint32_t r=ki*16+(lane&15);
        const uint32_t chk=nd*2+(lane>>4);
        const uint32_t o=soff(r,chk);
        uint32_t vh[4], vl[4];
        ldsm4t(vh, st+16384+o);
        ldsm4t(vl, st+24576+o);
        mma16816(O[2*nd],   ph, vh[0], vh[1]);
        mma16816(O[2*nd+1], ph, vh[2], vh[3]);
        mma16816(O[2*nd],   ph, vl[0], vl[1]);
        mma16816(O[2*nd+1], ph, vl[2], vl[3]);
        mma16816(O[2*nd],   pl, vh[0], vh[1]);
        mma16816(O[2*nd+1], pl, vh[2], vh[3]);
      }
    }
    __syncthreads();
    if(t+2<NT){ attn_loadkv(KVh,KVl,sb,tid,(size_t)b*KL+(size_t)(t+2)*64,h,t&1); CP_COMMIT(); }
  }

  #pragma unroll
  for(int hh=0;hh<2;hh++){
    const float inv=1.f/lrun[hh];
    const size_t grow=qrow0+wid*16+(lane>>2)+hh*8;
    #pragma unroll
    for(int nj=0;nj<8;nj++){
      const int gcol=h*64+nj*8+2*(lane&3);
      uint32_t lo, hi=pack2(O[nj][2*hh]*inv, O[nj][2*hh+1]*inv, lo);
      *(uint32_t*)(Ch+grow*DIM+gcol)=hi;
      *(uint32_t*)(Cl+grow*DIM+gcol)=lo;
    }
  }
}

// ---------------- launch ----------------
extern "C" void kernel_launch(void* const* d_in, const int* in_sizes, int n_in,
                              void* d_out, int out_size){
  const float* q   =(const float*)d_in[0];
  const float* kv  =(const float*)d_in[1];
  const int*   ids =(const int*)  d_in[3];
  const float* ln1s=(const float*)d_in[4];
  const float* ln1b=(const float*)d_in[5];
  const float* Wq  =(const float*)d_in[6];
  const float* Wkv =(const float*)d_in[7];
  const float* Wo  =(const float*)d_in[8];
  const float* ln2s=(const float*)d_in[9];
  const float* ln2b=(const float*)d_in[10];
  const float* W1  =(const float*)d_in[11];
  const float* W2  =(const float*)d_in[12];
  const float* pe  =(const float*)d_in[13];
  float* out=(float*)d_out;

#define SYM(v,s) void* v##_; cudaGetSymbolAddress(&v##_,s);
  SYM(wqh,w_q_h) SYM(wql,w_q_l) SYM(wkvh,w_kv_h) SYM(wkvl,w_kv_l)
  SYM(woh,w_o_h) SYM(wol,w_o_l) SYM(w1h,w_1_h)   SYM(w1l,w_1_l)
  SYM(w2h,w_2_h) SYM(w2l,w_2_l)
  SYM(qlh,g_qln_h) SYM(qll,g_qln_l) SYM(kph,g_kvpe_h) SYM(kpl,g_kvpe_l)
  SYM(qph,g_qp_h)  SYM(qpl,g_qp_l)  SYM(kvph,g_kvp_h) SYM(kvpl,g_kvp_l)
  SYM(cth,g_ctx_h) SYM(ctl,g_ctx_l) SYM(atf,g_attn)
  SYM(hbh,g_hb_h)  SYM(hbl,g_hb_l)  SYM(inh,g_in_h)   SYM(inl,g_in_l)
#undef SYM
#define BF(p) ((bf16*)p##_)
#define FL(p) ((float*)p##_)

  cudaFuncSetAttribute(mm_kernel<0>, cudaFuncAttributeMaxDynamicSharedMemorySize, MM_SMEM);
  cudaFuncSetAttribute(mm_kernel<1>, cudaFuncAttributeMaxDynamicSharedMemorySize, MM_SMEM);
  cudaFuncSetAttribute(mm_kernel<2>, cudaFuncAttributeMaxDynamicSharedMemorySize, MM_SMEM);
  cudaFuncSetAttribute(mm_kernel<3>, cudaFuncAttributeMaxDynamicSharedMemorySize, MM_SMEM);
  cudaFuncSetAttribute(attn_kernel,  cudaFuncAttributeMaxDynamicSharedMemorySize, AT_SMEM);

  dim3 tb(32,8);
  tsplit_kernel<<<dim3(DIM/32,DIM/32),tb>>>(Wq,  BF(wqh), BF(wql), DIM, DIM);
  tsplit_kernel<<<dim3(2*DIM/32,DIM/32),tb>>>(Wkv,BF(wkvh),BF(wkvl),DIM, 2*DIM);
  tsplit_kernel<<<dim3(DIM/32,DIM/32),tb>>>(Wo,  BF(woh), BF(wol), DIM, DIM);
  tsplit_kernel<<<dim3(INNER/32,DIM/32),tb>>>(W1,BF(w1h), BF(w1l), DIM, INNER);
  tsplit_kernel<<<dim3(DIM/32,INNER/32),tb>>>(W2,BF(w2h), BF(w2l), INNER, DIM);

  ln_split_kernel<<<MQ,256>>>(q, ln1s, ln1b, BF(qlh), BF(qll));
  kvpe_split_kernel<<<MKV,256>>>(kv, pe, ids, BF(kph), BF(kpl));

  // queries (scaled by 1/8 in epilogue, exact)
  mm_kernel<3><<<dim3(DIM/256,MQ/128),256,MM_SMEM>>>(BF(qlh),BF(qll),BF(wqh),BF(wql),
      nullptr,nullptr,BF(qph),BF(qpl),DIM,DIM);
  mm_kernel<0><<<dim3(2*DIM/256,MKV/128),256,MM_SMEM>>>(BF(kph),BF(kpl),BF(wkvh),BF(wkvl),
      nullptr,nullptr,BF(kvph),BF(kvpl),2*DIM,DIM);

  attn_kernel<<<dim3(QL/128,HEADS,BATCH),256,AT_SMEM>>>(BF(qph),BF(qpl),BF(kvph),BF(kvpl),
      BF(cth),BF(ctl));

  mm_kernel<1><<<dim3(DIM/256,MQ/128),256,MM_SMEM>>>(BF(cth),BF(ctl),BF(woh),BF(wol),
      q,FL(atf),nullptr,nullptr,DIM,DIM);
  ln_split_kernel<<<MQ,256>>>(FL(atf), ln2s, ln2b, BF(hbh), BF(hbl));
  mm_kernel<2><<<dim3(INNER/256,MQ/128),256,MM_SMEM>>>(BF(hbh),BF(hbl),BF(w1h),BF(w1l),
      nullptr,nullptr,BF(inh),BF(inl),INNER,DIM);
  mm_kernel<1><<<dim3(DIM/256,MQ/128),256,MM_SMEM>>>(BF(inh),BF(inl),BF(w2h),BF(w2l),
      FL(atf),out,nullptr,nullptr,DIM,INNER);
}

// round 8
// speedup vs baseline: 1.2254x; 1.2254x over previous
#include <cuda_runtime.h>
#include <cuda_bf16.h>
#include <cstdint>
#include <math.h>

#define DIM    1024
#define HEADS  16
#define DH     64
#define BATCH  2
#define QL     1024
#define KL     4096
#define INNER  4096
#define MQ     (BATCH*QL)
#define MKV    (BATCH*KL)
typedef __nv_bfloat16 bf16;

// ---------------- scratch ----------------
#define ALN __align__(256)
__device__ ALN bf16 w_q_h [DIM*DIM],    w_q_l [DIM*DIM];
__device__ ALN bf16 w_kv_h[2*DIM*DIM],  w_kv_l[2*DIM*DIM];
__device__ ALN bf16 w_o_h [DIM*DIM],    w_o_l [DIM*DIM];
__device__ ALN bf16 w_1_h [INNER*DIM],  w_1_l [INNER*DIM];
__device__ ALN bf16 w_2_h [DIM*INNER],  w_2_l [DIM*INNER];
__device__ ALN bf16 g_qln_h [MQ*DIM],   g_qln_l [MQ*DIM];
__device__ ALN bf16 g_kvpe_h[MKV*DIM],  g_kvpe_l[MKV*DIM];
__device__ ALN bf16 g_qp_h  [MQ*DIM],   g_qp_l  [MQ*DIM];
__device__ ALN bf16 g_kvp_h [MKV*2*DIM],g_kvp_l [MKV*2*DIM];
__device__ ALN bf16 g_ctx_h [MQ*DIM],   g_ctx_l [MQ*DIM];
__device__ ALN float g_attn [MQ*DIM];
__device__ ALN bf16 g_hb_h  [MQ*DIM],   g_hb_l  [MQ*DIM];
__device__ ALN bf16 g_in_h  [MQ*INNER], g_in_l  [MQ*INNER];

// ---------------- PTX helpers (sm_80-compatible only) ----------------
__device__ __forceinline__ uint32_t smem_u32(const void* p){ uint32_t a;
  asm("{ .reg .u64 t; cvta.to.shared.u64 t, %1; cvt.u32.u64 %0, t; }":"=r"(a):"l"(p)); return a; }
__device__ __forceinline__ void cp16(uint32_t d, const void* s){
  asm volatile("cp.async.cg.shared.global [%0],[%1],16;"::"r"(d),"l"(s)); }
#define CP_COMMIT() asm volatile("cp.async.commit_group;":::"memory")
#define CP_WAIT0()  asm volatile("cp.async.wait_group 0;":::"memory")
#define CP_WAIT1()  asm volatile("cp.async.wait_group 1;":::"memory")
#define CP_WAIT2()  asm volatile("cp.async.wait_group 2;":::"memory")

__device__ __forceinline__ void ldsm4(uint32_t* r, uint32_t a){
  asm volatile("ldmatrix.sync.aligned.m8n8.x4.shared.b16 {%0,%1,%2,%3},[%4];"
    :"=r"(r[0]),"=r"(r[1]),"=r"(r[2]),"=r"(r[3]):"r"(a));
}
__device__ __forceinline__ void ldsm4t(uint32_t* r, uint32_t a){
  asm volatile("ldmatrix.sync.aligned.m8n8.x4.trans.shared.b16 {%0,%1,%2,%3},[%4];"
    :"=r"(r[0]),"=r"(r[1]),"=r"(r[2]),"=r"(r[3]):"r"(a));
}
__device__ __forceinline__ void mma16816(float* d, const uint32_t* a, uint32_t b0, uint32_t b1){
  asm volatile("mma.sync.aligned.m16n8k16.row.col.f32.bf16.bf16.f32 "
    "{%0,%1,%2,%3},{%4,%5,%6,%7},{%8,%9},{%0,%1,%2,%3};"
    :"+f"(d[0]),"+f"(d[1]),"+f"(d[2]),"+f"(d[3])
    :"r"(a[0]),"r"(a[1]),"r"(a[2]),"r"(a[3]),"r"(b0),"r"(b1));
}
__device__ __forceinline__ uint32_t pack2(float a, float b, uint32_t& lo){
  bf16 ha=__float2bfloat16(a), hb=__float2bfloat16(b);
  bf16 la=__float2bfloat16(a-__bfloat162float(ha));
  bf16 lb=__float2bfloat16(b-__bfloat162float(hb));
  lo=(uint32_t)__bfloat16_as_ushort(la)|((uint32_t)__bfloat16_as_ushort(lb)<<16);
  return (uint32_t)__bfloat16_as_ushort(ha)|((uint32_t)__bfloat16_as_ushort(hb)<<16);
}
__device__ __forceinline__ float gelu_tanh(float x){
  return 0.5f*x*(1.0f+tanhf(0.7978845608028654f*(x+0.044715f*x*x*x)));
}
__device__ __forceinline__ uint32_t soff(uint32_t r, uint32_t ch){
  return r*128u + ((ch ^ (r & 7u)) << 4);
}

// ---------------- elementwise ----------------
__global__ void __launch_bounds__(256) ln_split_kernel(const float* __restrict__ x,
    const float* __restrict__ sc_, const float* __restrict__ bi_,
    bf16* __restrict__ oh, bf16* __restrict__ ol){
  const int row=blockIdx.x, t=threadIdx.x;
  const float4 v=((const float4*)(x+(size_t)row*DIM))[t];
  float s=v.x+v.y+v.z+v.w, ss=v.x*v.x+v.y*v.y+v.z*v.z+v.w*v.w;
  #pragma unroll
  for(int o=16;o;o>>=1){ s+=__shfl_xor_sync(~0u,s,o); ss+=__shfl_xor_sync(~0u,ss,o); }
  __shared__ float sm1[8], sm2[8];
  if((t&31)==0){ sm1[t>>5]=s; sm2[t>>5]=ss; }
  __syncthreads();
  float tot=0.f,tot2=0.f;
  #pragma unroll
  for(int i=0;i<8;i++){ tot+=sm1[i]; tot2+=sm2[i]; }
  const float mean=tot*(1.f/DIM), var=tot2*(1.f/DIM)-mean*mean, inv=rsqrtf(var+1e-6f);
  const float4 sc=((const float4*)sc_)[t], bi=((const float4*)bi_)[t];
  float o0=(v.x-mean)*inv*sc.x+bi.x, o1=(v.y-mean)*inv*sc.y+bi.y;
  float o2=(v.z-mean)*inv*sc.z+bi.z, o3=(v.w-mean)*inv*sc.w+bi.w;
  uint32_t l0,l1,h0=pack2(o0,o1,l0),h1=pack2(o2,o3,l1);
  ((uint2*)(oh+(size_t)row*DIM))[t]=make_uint2(h0,h1);
  ((uint2*)(ol+(size_t)row*DIM))[t]=make_uint2(l0,l1);
}

__global__ void __launch_bounds__(256) kvpe_split_kernel(const float* __restrict__ kv,
    const float* __restrict__ pe, const int* __restrict__ ids,
    bf16* __restrict__ oh, bf16* __restrict__ ol){
  const int row=blockIdx.x, t=threadIdx.x;
  const int id=ids[row];
  float4 a=((const float4*)(kv+(size_t)row*DIM))[t];
  const float4 p=((const float4*)(pe+(size_t)id*DIM))[t];
  a.x+=p.x; a.y+=p.y; a.z+=p.z; a.w+=p.w;
  uint32_t l0,l1,h0=pack2(a.x,a.y,l0),h1=pack2(a.z,a.w,l1);
  ((uint2*)(oh+(size_t)row*DIM))[t]=make_uint2(h0,h1);
  ((uint2*)(ol+(size_t)row*DIM))[t]=make_uint2(l0,l1);
}

__global__ void __launch_bounds__(256) tsplit_kernel(const float* __restrict__ W,
    bf16* __restrict__ Th, bf16* __restrict__ Tl, int K, int N){
  __shared__ float t[32][33];
  const int tx=threadIdx.x, ty=threadIdx.y;
  const int bx=blockIdx.x*32, by=blockIdx.y*32;
  #pragma unroll
  for(int yy=ty;yy<32;yy+=8) t[yy][tx]=W[(size_t)(by+yy)*N+bx+tx];
  __syncthreads();
  #pragma unroll
  for(int yy=ty;yy<32;yy+=8){
    float v=t[tx][yy];
    bf16 h=__float2bfloat16(v), l=__float2bfloat16(v-__bfloat162float(h));
    const size_t idx=(size_t)(bx+yy)*K+by+tx;
    Th[idx]=h; Tl[idx]=l;
  }
}

// ---------------- HMMA GEMM: C[M,N] = A[M,K] @ Bt[N,K]^T ----------------
// tile 128x128x64, 3-stage cp.async pipeline
// stage (64KB): Ah@0, Al@16384, Bh@32768, Bl@49152
#define MM_STAGE 65536
#define MM_SMEM  (3*MM_STAGE)

__device__ __forceinline__ void mm_load(const bf16* Ah,const bf16* Al,const bf16* Bh,const bf16* Bl,
    uint32_t sb,int tid,int row0,int col0,int K,int s){
  const int k0=s*64; const uint32_t st=sb+(s%3)*MM_STAGE;
  #pragma unroll
  for(int i=0;i<4;i++){
    int id=tid+256*i; uint32_t r=id>>3, c=id&7; uint32_t so=soff(r,c);
    cp16(st+so,       Ah+(size_t)(row0+r)*K+k0+c*8);
    cp16(st+16384+so, Al+(size_t)(row0+r)*K+k0+c*8);
    cp16(st+32768+so, Bh+(size_t)(col0+r)*K+k0+c*8);
    cp16(st+49152+so, Bl+(size_t)(col0+r)*K+k0+c*8);
  }
}

// EPI: 0=split-bf16, 1=+residual fp32, 2=gelu split-bf16, 3=scale 0.125 split-bf16
template <int EPI>
__global__ void __launch_bounds__(256,1) mm_kernel(const bf16* __restrict__ Ah,const bf16* __restrict__ Al,
    const bf16* __restrict__ Bh,const bf16* __restrict__ Bl,
    const float* __restrict__ R, float* __restrict__ Cf,
    bf16* __restrict__ Ch, bf16* __restrict__ Cl, int N, int K){
  extern __shared__ char smc[];
  const uint32_t sb=smem_u32(smc);
  const int tid=threadIdx.x, wid=tid>>5, lane=tid&31;
  const int row0=blockIdx.y*128, col0=blockIdx.x*128;
  const int m0=(wid>>2)*64, n0=(wid&3)*32;

  float acc[4][4][4];
  #pragma unroll
  for(int i=0;i<4;i++)
    #pragma unroll
    for(int j=0;j<4;j++)
      #pragma unroll
      for(int k=0;k<4;k++) acc[i][j][k]=0.f;

  const int S=K/64;   // >= 16 for all our GEMMs
  mm_load(Ah,Al,Bh,Bl,sb,tid,row0,col0,K,0); CP_COMMIT();
  mm_load(Ah,Al,Bh,Bl,sb,tid,row0,col0,K,1); CP_COMMIT();
  mm_load(Ah,Al,Bh,Bl,sb,tid,row0,col0,K,2); CP_COMMIT();

  for(int s=0;s<S;s++){
    CP_WAIT2();            // stages s+1, s+2 may remain outstanding -> stage s ready
    __syncthreads();
    const uint32_t st=sb+(s%3)*MM_STAGE;
    #pragma unroll
    for(int kk=0;kk<4;kk++){
      const uint32_t chk=kk*2+(lane>>4);
      uint32_t bh[2][4], bl[2][4];
      #pragma unroll
      for(int ni=0;ni<2;ni++){
        const uint32_t r=n0+ni*16+(lane&15);
        const uint32_t o=soff(r,chk);
        ldsm4(bh[ni], st+32768+o);
        ldsm4(bl[ni], st+49152+o);
      }
      #pragma unroll
      for(int mi=0;mi<4;mi++){
        const uint32_t r=m0+mi*16+(lane&15);
        const uint32_t o=soff(r,chk);
        uint32_t ah[4], al[4];
        ldsm4(ah, st+o);
        ldsm4(al, st+16384+o);
        #pragma unroll
        for(int nj=0;nj<4;nj++){
          const uint32_t b0h=bh[nj>>1][nj&1], b1h=bh[nj>>1][(nj&1)+2];
          const uint32_t b0l=bl[nj>>1][nj&1], b1l=bl[nj>>1][(nj&1)+2];
          mma16816(acc[mi][nj], ah, b0h, b1h);
          mma16816(acc[mi][nj], ah, b0l, b1l);
          mma16816(acc[mi][nj], al, b0h, b1h);
        }
      }
    }
    __syncthreads();
    if(s+3<S) mm_load(Ah,Al,Bh,Bl,sb,tid,row0,col0,K,s+3);
    CP_COMMIT();           // always commit (possibly empty) to keep group count aligned
  }

  #pragma unroll
  for(int mi=0;mi<4;mi++){
    #pragma unroll
    for(int h=0;h<2;h++){
      const int grow=row0+m0+mi*16+(lane>>2)+h*8;
      #pragma unroll
      for(int nj=0;nj<4;nj++){
        const int gcol=col0+n0+nj*8+2*(lane&3);
        const float v0=acc[mi][nj][2*h], v1=acc[mi][nj][2*h+1];
        if(EPI==1){
          float2 rv=*(const float2*)(R+(size_t)grow*N+gcol);
          *(float2*)(Cf+(size_t)grow*N+gcol)=make_float2(v0+rv.x, v1+rv.y);
        } else {
          float a=v0,b=v1;
          if(EPI==2){ a=gelu_tanh(a); b=gelu_tanh(b); }
          if(EPI==3){ a*=0.125f; b*=0.125f; }
          uint32_t lo, hi=pack2(a,b,lo);
          *(uint32_t*)(Ch+(size_t)grow*N+gcol)=hi;
          *(uint32_t*)(Cl+(size_t)grow*N+gcol)=lo;
        }
      }
    }
  }
}

// ---------------- FA2 attention (HMMA), 128 threads, 2 CTAs/SM ----------------
// smem: QH @0 (16KB), QL @16384; stage buf @32768+buf*32768: KH+0, KL+8192, VH+16384, VL+24576
#define AT_SMEM 98304

__device__ __forceinline__ void attn_loadkv(const bf16* KVh,const bf16* KVl,
    uint32_t sb,int tid,size_t kr0,int h,int buf){
  const uint32_t st=sb+32768+buf*32768;
  #pragma unroll
  for(int i=0;i<4;i++){
    int id=tid+128*i; uint32_t r=id>>3, c=id&7; uint32_t so=soff(r,c);
    const size_t g=(kr0+r)*2048 + (size_t)h*64 + c*8;
    cp16(st+so,        KVh+g);
    cp16(st+8192+so,   KVl+g);
    cp16(st+16384+so,  KVh+g+1024);
    cp16(st+24576+so,  KVl+g+1024);
  }
}

__global__ void __launch_bounds__(128,2) attn_kernel(const bf16* __restrict__ Qh,const bf16* __restrict__ Ql,
    const bf16* __restrict__ KVh,const bf16* __restrict__ KVl,
    bf16* __restrict__ Ch, bf16* __restrict__ Cl){
  extern __shared__ char smc[];
  const uint32_t sb=smem_u32(smc);
  const int tid=threadIdx.x, wid=tid>>5, lane=tid&31;
  const int qt=blockIdx.x, h=blockIdx.y, b=blockIdx.z;
  const size_t qrow0=(size_t)(b*QL+qt*128);

  #pragma unroll
  for(int i=0;i<8;i++){
    int id=tid+128*i; uint32_t r=id>>3, c=id&7; uint32_t so=soff(r,c);
    const size_t g=(qrow0+r)*DIM + (size_t)h*64 + c*8;
    cp16(sb+so,       Qh+g);
    cp16(sb+16384+so, Ql+g);
  }
  attn_loadkv(KVh,KVl,sb,tid,(size_t)b*KL,h,0); CP_COMMIT();
  attn_loadkv(KVh,KVl,sb,tid,(size_t)b*KL+64,h,1); CP_COMMIT();

  float O[2][8][4];
  #pragma unroll
  for(int i=0;i<2;i++)
    #pragma unroll
    for(int j=0;j<8;j++)
      #pragma unroll
      for(int k=0;k<4;k++) O[i][j][k]=0.f;
  float mrun[2][2]={{-1e30f,-1e30f},{-1e30f,-1e30f}};
  float lrun[2][2]={{0.f,0.f},{0.f,0.f}};

  const int NT=KL/64;
  for(int t=0;t<NT;t++){
    if(t+1<NT) CP_WAIT1(); else CP_WAIT0();
    __syncthreads();
    const uint32_t st=sb+32768+(t&1)*32768;

    // ---- S = Q @ K^T (3-split), 32 q-rows per warp ----
    float S[2][8][4];
    #pragma unroll
    for(int i=0;i<2;i++)
      #pragma unroll
      for(int j=0;j<8;j++)
        #pragma unroll
        for(int k=0;k<4;k++) S[i][j][k]=0.f;
    #pragma unroll
    for(int kk=0;kk<4;kk++){
      const uint32_t chk=kk*2+(lane>>4);
      uint32_t qh[2][4], ql[2][4];
      #pragma unroll
      for(int mi=0;mi<2;mi++){
        const uint32_t r=wid*32+mi*16+(lane&15);
        const uint32_t o=soff(r,chk);
        ldsm4(qh[mi], sb+o);
        ldsm4(ql[mi], sb+16384+o);
      }
      #pragma unroll
      for(int nk=0;nk<4;nk++){
        const uint32_t r=nk*16+(lane&15);
        const uint32_t o=soff(r,chk);
        uint32_t kh[4], kl[4];
        ldsm4(kh, st+o);
        ldsm4(kl, st+8192+o);
        #pragma unroll
        for(int mi=0;mi<2;mi++){
          mma16816(S[mi][2*nk],   qh[mi], kh[0], kh[2]);
          mma16816(S[mi][2*nk+1], qh[mi], kh[1], kh[3]);
          mma16816(S[mi][2*nk],   qh[mi], kl[0], kl[2]);
          mma16816(S[mi][2*nk+1], qh[mi], kl[1], kl[3]);
          mma16816(S[mi][2*nk],   ql[mi], kh[0], kh[2]);
          mma16816(S[mi][2*nk+1], ql[mi], kh[1], kh[3]);
        }
      }
    }

    // ---- online softmax (1/sqrt(dh) folded into Q projection) ----
    float alpha[2][2];
    #pragma unroll
    for(int mi=0;mi<2;mi++)
      #pragma unroll
      for(int hh=0;hh<2;hh++){
        float mx=-1e30f;
        #pragma unroll
        for(int nj=0;nj<8;nj++){ mx=fmaxf(mx,S[mi][nj][2*hh]); mx=fmaxf(mx,S[mi][nj][2*hh+1]); }
        mx=fmaxf(mx,__shfl_xor_sync(~0u,mx,1));
        mx=fmaxf(mx,__shfl_xor_sync(~0u,mx,2));
        const float mn=fmaxf(mrun[mi][hh],mx);
        alpha[mi][hh]=__expf(mrun[mi][hh]-mn);
        mrun[mi][hh]=mn;
        float sum=0.f;
        #pragma unroll
        for(int nj=0;nj<8;nj++){
          float e0=__expf(S[mi][nj][2*hh]-mn), e1=__expf(S[mi][nj][2*hh+1]-mn);
          S[mi][nj][2*hh]=e0; S[mi][nj][2*hh+1]=e1; sum+=e0+e1;
        }
        sum+=__shfl_xor_sync(~0u,sum,1);
        sum+=__shfl_xor_sync(~0u,sum,2);
        lrun[mi][hh]=lrun[mi][hh]*alpha[mi][hh]+sum;
        #pragma unroll
        for(int nj=0;nj<8;nj++){
          O[mi][nj][2*hh]  *=alpha[mi][hh];
          O[mi][nj][2*hh+1]*=alpha[mi][hh];
        }
      }

    // ---- O += P @ V (3-split), V via ldmatrix.trans ----
    #pragma unroll
    for(int ki=0;ki<4;ki++){
      uint32_t ph[2][4], pl[2][4];
      #pragma unroll
      for(int mi=0;mi<2;mi++){
        ph[mi][0]=pack2(S[mi][2*ki][0],  S[mi][2*ki][1],  pl[mi][0]);
        ph[mi][1]=pack2(S[mi][2*ki][2],  S[mi][2*ki][3],  pl[mi][1]);
        ph[mi][2]=pack2(S[mi][2*ki+1][0],S[mi][2*ki+1][1],pl[mi][2]);
        ph[mi][3]=pack2(S[mi][2*ki+1][2],S[mi][2*ki+1][3],pl[mi][3]);
      }
      #pragma unroll
      for(int nd=0;nd<4;nd++){
        const uint32_t r=ki*16+(lane&15);
        const uint32_t chk=nd*2+(lane>>4);
        const uint32_t o=soff(r,chk);
        uint32_t vh[4], vl[4];
        ldsm4t(vh, st+16384+o);
        ldsm4t(vl, st+24576+o);
        #pragma unroll
        for(int mi=0;mi<2;mi++){
          mma16816(O[mi][2*nd],   ph[mi], vh[0], vh[1]);
          mma16816(O[mi][2*nd+1], ph[mi], vh[2], vh[3]);
          mma16816(O[mi][2*nd],   ph[mi], vl[0], vl[1]);
          mma16816(O[mi][2*nd+1], ph[mi], vl[2], vl[3]);
          mma16816(O[mi][2*nd],   pl[mi], vh[0], vh[1]);
          mma16816(O[mi][2*nd+1], pl[mi], vh[2], vh[3]);
        }
      }
    }
    __syncthreads();
    if(t+2<NT){ attn_loadkv(KVh,KVl,sb,tid,(size_t)b*KL+(size_t)(t+2)*64,h,t&1); CP_COMMIT(); }
  }

  #pragma unroll
  for(int mi=0;mi<2;mi++)
    #pragma unroll
    for(int hh=0;hh<2;hh++){
      const float inv=1.f/lrun[mi][hh];
      const size_t grow=qrow0+wid*32+mi*16+(lane>>2)+hh*8;
      #pragma unroll
      for(int nj=0;nj<8;nj++){
        const int gcol=h*64+nj*8+2*(lane&3);
        uint32_t lo, hi=pack2(O[mi][nj][2*hh]*inv, O[mi][nj][2*hh+1]*inv, lo);
        *(uint32_t*)(Ch+grow*DIM+gcol)=hi;
        *(uint32_t*)(Cl+grow*DIM+gcol)=lo;
      }
    }
}

// ---------------- launch ----------------
extern "C" void kernel_launch(void* const* d_in, const int* in_sizes, int n_in,
                              void* d_out, int out_size){
  const float* q   =(const float*)d_in[0];
  const float* kv  =(const float*)d_in[1];
  const int*   ids =(const int*)  d_in[3];
  const float* ln1s=(const float*)d_in[4];
  const float* ln1b=(const float*)d_in[5];
  const float* Wq  =(const float*)d_in[6];
  const float* Wkv =(const float*)d_in[7];
  const float* Wo  =(const float*)d_in[8];
  const float* ln2s=(const float*)d_in[9];
  const float* ln2b=(const float*)d_in[10];
  const float* W1  =(const float*)d_in[11];
  const float* W2  =(const float*)d_in[12];
  const float* pe  =(const float*)d_in[13];
  float* out=(float*)d_out;

#define SYM(v,s) void* v##_; cudaGetSymbolAddress(&v##_,s);
  SYM(wqh,w_q_h) SYM(wql,w_q_l) SYM(wkvh,w_kv_h) SYM(wkvl,w_kv_l)
  SYM(woh,w_o_h) SYM(wol,w_o_l) SYM(w1h,w_1_h)   SYM(w1l,w_1_l)
  SYM(w2h,w_2_h) SYM(w2l,w_2_l)
  SYM(qlh,g_qln_h) SYM(qll,g_qln_l) SYM(kph,g_kvpe_h) SYM(kpl,g_kvpe_l)
  SYM(qph,g_qp_h)  SYM(qpl,g_qp_l)  SYM(kvph,g_kvp_h) SYM(kvpl,g_kvp_l)
  SYM(cth,g_ctx_h) SYM(ctl,g_ctx_l) SYM(atf,g_attn)
  SYM(hbh,g_hb_h)  SYM(hbl,g_hb_l)  SYM(inh,g_in_h)   SYM(inl,g_in_l)
#undef SYM
#define BF(p) ((bf16*)p##_)
#define FL(p) ((float*)p##_)

  cudaFuncSetAttribute(mm_kernel<0>, cudaFuncAttributeMaxDynamicSharedMemorySize, MM_SMEM);
  cudaFuncSetAttribute(mm_kernel<1>, cudaFuncAttributeMaxDynamicSharedMemorySize, MM_SMEM);
  cudaFuncSetAttribute(mm_kernel<2>, cudaFuncAttributeMaxDynamicSharedMemorySize, MM_SMEM);
  cudaFuncSetAttribute(mm_kernel<3>, cudaFuncAttributeMaxDynamicSharedMemorySize, MM_SMEM);
  cudaFuncSetAttribute(attn_kernel,  cudaFuncAttributeMaxDynamicSharedMemorySize, AT_SMEM);

  dim3 tb(32,8);
  tsplit_kernel<<<dim3(DIM/32,DIM/32),tb>>>(Wq,  BF(wqh), BF(wql), DIM, DIM);
  tsplit_kernel<<<dim3(2*DIM/32,DIM/32),tb>>>(Wkv,BF(wkvh),BF(wkvl),DIM, 2*DIM);
  tsplit_kernel<<<dim3(DIM/32,DIM/32),tb>>>(Wo,  BF(woh), BF(wol), DIM, DIM);
  tsplit_kernel<<<dim3(INNER/32,DIM/32),tb>>>(W1,BF(w1h), BF(w1l), DIM, INNER);
  tsplit_kernel<<<dim3(DIM/32,INNER/32),tb>>>(W2,BF(w2h), BF(w2l), INNER, DIM);

  ln_split_kernel<<<MQ,256>>>(q, ln1s, ln1b, BF(qlh), BF(qll));
  kvpe_split_kernel<<<MKV,256>>>(kv, pe, ids, BF(kph), BF(kpl));

  // queries (scaled by 1/8 in epilogue, exact)
  mm_kernel<3><<<dim3(DIM/128,MQ/128),256,MM_SMEM>>>(BF(qlh),BF(qll),BF(wqh),BF(wql),
      nullptr,nullptr,BF(qph),BF(qpl),DIM,DIM);
  mm_kernel<0><<<dim3(2*DIM/128,MKV/128),256,MM_SMEM>>>(BF(kph),BF(kpl),BF(wkvh),BF(wkvl),
      nullptr,nullptr,BF(kvph),BF(kvpl),2*DIM,DIM);

  attn_kernel<<<dim3(QL/128,HEADS,BATCH),128,AT_SMEM>>>(BF(qph),BF(qpl),BF(kvph),BF(kvpl),
      BF(cth),BF(ctl));

  mm_kernel<1><<<dim3(DIM/128,MQ/128),256,MM_SMEM>>>(BF(cth),BF(ctl),BF(woh),BF(wol),
      q,FL(atf),nullptr,nullptr,DIM,DIM);
  ln_split_kernel<<<MQ,256>>>(FL(atf), ln2s, ln2b, BF(hbh), BF(hbl));
  mm_kernel<2><<<dim3(INNER/128,MQ/128),256,MM_SMEM>>>(BF(hbh),BF(hbl),BF(w1h),BF(w1l),
      nullptr,nullptr,BF(inh),BF(inl),INNER,DIM);
  mm_kernel<1><<<dim3(DIM/128,MQ/128),256,MM_SMEM>>>(BF(inh),BF(inl),BF(w2h),BF(w2l),
      FL(atf),out,nullptr,nullptr,DIM,INNER);
}

// round 9
// speedup vs baseline: 1.3793x; 1.1256x over previous
#include <cuda_runtime.h>
#include <cuda_bf16.h>
#include <cuda_fp16.h>
#include <cstdint>
#include <math.h>

#define DIM    1024
#define HEADS  16
#define DH     64
#define BATCH  2
#define QL     1024
#define KL     4096
#define INNER  4096
#define MQ     (BATCH*QL)
#define MKV    (BATCH*KL)
typedef __nv_bfloat16 bf16;

// 0.125 * log2(e): folded into Q projection so softmax works in exp2 domain
#define SCALEC 0.18033688011112042f

// ---------------- scratch ----------------
#define ALN __align__(256)
__device__ ALN bf16 w_q_h [DIM*DIM],    w_q_l [DIM*DIM];
__device__ ALN bf16 w_kv_h[2*DIM*DIM],  w_kv_l[2*DIM*DIM];
__device__ ALN bf16 w_o_h [DIM*DIM],    w_o_l [DIM*DIM];
__device__ ALN __half w_1_h [INNER*DIM], w_1_l [INNER*DIM];   // fp16, pre-scaled x32
__device__ ALN __half w_2_h [DIM*INNER], w_2_l [DIM*INNER];   // fp16, pre-scaled x32
__device__ ALN bf16 g_qln_h [MQ*DIM],   g_qln_l [MQ*DIM];
__device__ ALN bf16 g_kvpe_h[MKV*DIM],  g_kvpe_l[MKV*DIM];
__device__ ALN bf16 g_qp_h  [MQ*DIM],   g_qp_l  [MQ*DIM];
__device__ ALN bf16 g_kvp_h [MKV*2*DIM],g_kvp_l [MKV*2*DIM];
__device__ ALN bf16 g_ctx_h [MQ*DIM],   g_ctx_l [MQ*DIM];
__device__ ALN float g_attn [MQ*DIM];
__device__ ALN __half g_hb  [MQ*DIM];                          // fp16 single (LN2 out)
__device__ ALN __half g_in  [MQ*INNER];                        // fp16 single (gelu out)

// ---------------- PTX helpers (sm_80-compatible only) ----------------
__device__ __forceinline__ uint32_t smem_u32(const void* p){ uint32_t a;
  asm("{ .reg .u64 t; cvta.to.shared.u64 t, %1; cvt.u32.u64 %0, t; }":"=r"(a):"l"(p)); return a; }
__device__ __forceinline__ void cp16(uint32_t d, const void* s){
  asm volatile("cp.async.cg.shared.global [%0],[%1],16;"::"r"(d),"l"(s)); }
#define CP_COMMIT() asm volatile("cp.async.commit_group;":::"memory")
#define CP_WAIT0()  asm volatile("cp.async.wait_group 0;":::"memory")
#define CP_WAIT1()  asm volatile("cp.async.wait_group 1;":::"memory")
#define CP_WAIT2()  asm volatile("cp.async.wait_group 2;":::"memory")

__device__ __forceinline__ void ldsm4(uint32_t* r, uint32_t a){
  asm volatile("ldmatrix.sync.aligned.m8n8.x4.shared.b16 {%0,%1,%2,%3},[%4];"
    :"=r"(r[0]),"=r"(r[1]),"=r"(r[2]),"=r"(r[3]):"r"(a));
}
__device__ __forceinline__ void ldsm4t(uint32_t* r, uint32_t a){
  asm volatile("ldmatrix.sync.aligned.m8n8.x4.trans.shared.b16 {%0,%1,%2,%3},[%4];"
    :"=r"(r[0]),"=r"(r[1]),"=r"(r[2]),"=r"(r[3]):"r"(a));
}
// bf16 MMA
__device__ __forceinline__ void mma16816(float* d, const uint32_t* a, uint32_t b0, uint32_t b1){
  asm volatile("mma.sync.aligned.m16n8k16.row.col.f32.bf16.bf16.f32 "
    "{%0,%1,%2,%3},{%4,%5,%6,%7},{%8,%9},{%0,%1,%2,%3};"
    :"+f"(d[0]),"+f"(d[1]),"+f"(d[2]),"+f"(d[3])
    :"r"(a[0]),"r"(a[1]),"r"(a[2]),"r"(a[3]),"r"(b0),"r"(b1));
}
// fp16 MMA
__device__ __forceinline__ void mma16816h(float* d, const uint32_t* a, uint32_t b0, uint32_t b1){
  asm volatile("mma.sync.aligned.m16n8k16.row.col.f32.f16.f16.f32 "
    "{%0,%1,%2,%3},{%4,%5,%6,%7},{%8,%9},{%0,%1,%2,%3};"
    :"+f"(d[0]),"+f"(d[1]),"+f"(d[2]),"+f"(d[3])
    :"r"(a[0]),"r"(a[1]),"r"(a[2]),"r"(a[3]),"r"(b0),"r"(b1));
}
__device__ __forceinline__ uint32_t pack2(float a, float b, uint32_t& lo){
  bf16 ha=__float2bfloat16(a), hb=__float2bfloat16(b);
  bf16 la=__float2bfloat16(a-__bfloat162float(ha));
  bf16 lb=__float2bfloat16(b-__bfloat162float(hb));
  lo=(uint32_t)__bfloat16_as_ushort(la)|((uint32_t)__bfloat16_as_ushort(lb)<<16);
  return (uint32_t)__bfloat16_as_ushort(ha)|((uint32_t)__bfloat16_as_ushort(hb)<<16);
}
__device__ __forceinline__ uint32_t packh(float a, float b){
  __half2 h=__floats2half2_rn(a,b);
  return *(uint32_t*)&h;
}
__device__ __forceinline__ float ex2(float x){
  float r; asm("ex2.approx.ftz.f32 %0,%1;":"=f"(r):"f"(x)); return r;
}
__device__ __forceinline__ float gelu_tanh(float x){
  return 0.5f*x*(1.0f+tanhf(0.7978845608028654f*(x+0.044715f*x*x*x)));
}
__device__ __forceinline__ uint32_t soff(uint32_t r, uint32_t ch){
  return r*128u + ((ch ^ (r & 7u)) << 4);
}

// ---------------- elementwise ----------------
__global__ void __launch_bounds__(256) ln_split_kernel(const float* __restrict__ x,
    const float* __restrict__ sc_, const float* __restrict__ bi_,
    bf16* __restrict__ oh, bf16* __restrict__ ol){
  const int row=blockIdx.x, t=threadIdx.x;
  const float4 v=((const float4*)(x+(size_t)row*DIM))[t];
  float s=v.x+v.y+v.z+v.w, ss=v.x*v.x+v.y*v.y+v.z*v.z+v.w*v.w;
  #pragma unroll
  for(int o=16;o;o>>=1){ s+=__shfl_xor_sync(~0u,s,o); ss+=__shfl_xor_sync(~0u,ss,o); }
  __shared__ float sm1[8], sm2[8];
  if((t&31)==0){ sm1[t>>5]=s; sm2[t>>5]=ss; }
  __syncthreads();
  float tot=0.f,tot2=0.f;
  #pragma unroll
  for(int i=0;i<8;i++){ tot+=sm1[i]; tot2+=sm2[i]; }
  const float mean=tot*(1.f/DIM), var=tot2*(1.f/DIM)-mean*mean, inv=rsqrtf(var+1e-6f);
  const float4 sc=((const float4*)sc_)[t], bi=((const float4*)bi_)[t];
  float o0=(v.x-mean)*inv*sc.x+bi.x, o1=(v.y-mean)*inv*sc.y+bi.y;
  float o2=(v.z-mean)*inv*sc.z+bi.z, o3=(v.w-mean)*inv*sc.w+bi.w;
  uint32_t l0,l1,h0=pack2(o0,o1,l0),h1=pack2(o2,o3,l1);
  ((uint2*)(oh+(size_t)row*DIM))[t]=make_uint2(h0,h1);
  ((uint2*)(ol+(size_t)row*DIM))[t]=make_uint2(l0,l1);
}

// LN -> single fp16 (for 2-pass FFN consumer)
__global__ void __launch_bounds__(256) ln_half_kernel(const float* __restrict__ x,
    const float* __restrict__ sc_, const float* __restrict__ bi_,
    __half* __restrict__ oh){
  const int row=blockIdx.x, t=threadIdx.x;
  const float4 v=((const float4*)(x+(size_t)row*DIM))[t];
  float s=v.x+v.y+v.z+v.w, ss=v.x*v.x+v.y*v.y+v.z*v.z+v.w*v.w;
  #pragma unroll
  for(int o=16;o;o>>=1){ s+=__shfl_xor_sync(~0u,s,o); ss+=__shfl_xor_sync(~0u,ss,o); }
  __shared__ float sm1[8], sm2[8];
  if((t&31)==0){ sm1[t>>5]=s; sm2[t>>5]=ss; }
  __syncthreads();
  float tot=0.f,tot2=0.f;
  #pragma unroll
  for(int i=0;i<8;i++){ tot+=sm1[i]; tot2+=sm2[i]; }
  const float mean=tot*(1.f/DIM), var=tot2*(1.f/DIM)-mean*mean, inv=rsqrtf(var+1e-6f);
  const float4 sc=((const float4*)sc_)[t], bi=((const float4*)bi_)[t];
  float o0=(v.x-mean)*inv*sc.x+bi.x, o1=(v.y-mean)*inv*sc.y+bi.y;
  float o2=(v.z-mean)*inv*sc.z+bi.z, o3=(v.w-mean)*inv*sc.w+bi.w;
  ((uint2*)(oh+(size_t)row*DIM))[t]=make_uint2(packh(o0,o1),packh(o2,o3));
}

__global__ void __launch_bounds__(256) kvpe_split_kernel(const float* __restrict__ kv,
    const float* __restrict__ pe, const int* __restrict__ ids,
    bf16* __restrict__ oh, bf16* __restrict__ ol){
  const int row=blockIdx.x, t=threadIdx.x;
  const int id=ids[row];
  float4 a=((const float4*)(kv+(size_t)row*DIM))[t];
  const float4 p=((const float4*)(pe+(size_t)id*DIM))[t];
  a.x+=p.x; a.y+=p.y; a.z+=p.z; a.w+=p.w;
  uint32_t l0,l1,h0=pack2(a.x,a.y,l0),h1=pack2(a.z,a.w,l1);
  ((uint2*)(oh+(size_t)row*DIM))[t]=make_uint2(h0,h1);
  ((uint2*)(ol+(size_t)row*DIM))[t]=make_uint2(l0,l1);
}

// W[K,N] -> Wt[N,K] split hi/lo (bf16)
__global__ void __launch_bounds__(256) tsplit_kernel(const float* __restrict__ W,
    bf16* __restrict__ Th, bf16* __restrict__ Tl, int K, int N){
  __shared__ float t[32][33];
  const int tx=threadIdx.x, ty=threadIdx.y;
  const int bx=blockIdx.x*32, by=blockIdx.y*32;
  #pragma unroll
  for(int yy=ty;yy<32;yy+=8) t[yy][tx]=W[(size_t)(by+yy)*N+bx+tx];
  __syncthreads();
  #pragma unroll
  for(int yy=ty;yy<32;yy+=8){
    float v=t[tx][yy];
    bf16 h=__float2bfloat16(v), l=__float2bfloat16(v-__bfloat162float(h));
    const size_t idx=(size_t)(bx+yy)*K+by+tx;
    Th[idx]=h; Tl[idx]=l;
  }
}

// W[K,N] -> Wt[N,K] split hi/lo (fp16, scaled x32 so lo stays in normal range)
__global__ void __launch_bounds__(256) tsplit_h_kernel(const float* __restrict__ W,
    __half* __restrict__ Th, __half* __restrict__ Tl, int K, int N){
  __shared__ float t[32][33];
  const int tx=threadIdx.x, ty=threadIdx.y;
  const int bx=blockIdx.x*32, by=blockIdx.y*32;
  #pragma unroll
  for(int yy=ty;yy<32;yy+=8) t[yy][tx]=W[(size_t)(by+yy)*N+bx+tx];
  __syncthreads();
  #pragma unroll
  for(int yy=ty;yy<32;yy+=8){
    float v=t[tx][yy]*32.0f;
    __half h=__float2half_rn(v);
    __half l=__float2half_rn(v-__half2float(h));
    const size_t idx=(size_t)(bx+yy)*K+by+tx;
    Th[idx]=h; Tl[idx]=l;
  }
}

// ---------------- bf16 3-pass HMMA GEMM: C[M,N] = A[M,K] @ Bt[N,K]^T ----------------
// tile 128x128x64, 3-stage cp.async pipeline; stage (64KB): Ah@0, Al@16384, Bh@32768, Bl@49152
#define MM_STAGE 65536
#define MM_SMEM  (3*MM_STAGE)

__device__ __forceinline__ void mm_load(const bf16* Ah,const bf16* Al,const bf16* Bh,const bf16* Bl,
    uint32_t sb,int tid,int row0,int col0,int K,int s){
  const int k0=s*64; const uint32_t st=sb+(s%3)*MM_STAGE;
  #pragma unroll
  for(int i=0;i<4;i++){
    int id=tid+256*i; uint32_t r=id>>3, c=id&7; uint32_t so=soff(r,c);
    cp16(st+so,       Ah+(size_t)(row0+r)*K+k0+c*8);
    cp16(st+16384+so, Al+(size_t)(row0+r)*K+k0+c*8);
    cp16(st+32768+so, Bh+(size_t)(col0+r)*K+k0+c*8);
    cp16(st+49152+so, Bl+(size_t)(col0+r)*K+k0+c*8);
  }
}

// EPI: 0=split-bf16, 1=+residual fp32, 3=scale SCALEC split-bf16
template <int EPI>
__global__ void __launch_bounds__(256,1) mm_kernel(const bf16* __restrict__ Ah,const bf16* __restrict__ Al,
    const bf16* __restrict__ Bh,const bf16* __restrict__ Bl,
    const float* __restrict__ R, float* __restrict__ Cf,
    bf16* __restrict__ Ch, bf16* __restrict__ Cl, int N, int K){
  extern __shared__ char smc[];
  const uint32_t sb=smem_u32(smc);
  const int tid=threadIdx.x, wid=tid>>5, lane=tid&31;
  const int row0=blockIdx.y*128, col0=blockIdx.x*128;
  const int m0=(wid>>2)*64, n0=(wid&3)*32;

  float acc[4][4][4];
  #pragma unroll
  for(int i=0;i<4;i++)
    #pragma unroll
    for(int j=0;j<4;j++)
      #pragma unroll
      for(int k=0;k<4;k++) acc[i][j][k]=0.f;

  const int S=K/64;
  mm_load(Ah,Al,Bh,Bl,sb,tid,row0,col0,K,0); CP_COMMIT();
  mm_load(Ah,Al,Bh,Bl,sb,tid,row0,col0,K,1); CP_COMMIT();
  mm_load(Ah,Al,Bh,Bl,sb,tid,row0,col0,K,2); CP_COMMIT();

  for(int s=0;s<S;s++){
    CP_WAIT2();
    __syncthreads();
    const uint32_t st=sb+(s%3)*MM_STAGE;
    #pragma unroll
    for(int kk=0;kk<4;kk++){
      const uint32_t chk=kk*2+(lane>>4);
      uint32_t bh[2][4], bl[2][4];
      #pragma unroll
      for(int ni=0;ni<2;ni++){
        const uint32_t r=n0+ni*16+(lane&15);
        const uint32_t o=soff(r,chk);
        ldsm4(bh[ni], st+32768+o);
        ldsm4(bl[ni], st+49152+o);
      }
      #pragma unroll
      for(int mi=0;mi<4;mi++){
        const uint32_t r=m0+mi*16+(lane&15);
        const uint32_t o=soff(r,chk);
        uint32_t ah[4], al[4];
        ldsm4(ah, st+o);
        ldsm4(al, st+16384+o);
        #pragma unroll
        for(int nj=0;nj<4;nj++){
          const uint32_t b0h=bh[nj>>1][nj&1], b1h=bh[nj>>1][(nj&1)+2];
          const uint32_t b0l=bl[nj>>1][nj&1], b1l=bl[nj>>1][(nj&1)+2];
          mma16816(acc[mi][nj], ah, b0h, b1h);
          mma16816(acc[mi][nj], ah, b0l, b1l);
          mma16816(acc[mi][nj], al, b0h, b1h);
        }
      }
    }
    __syncthreads();
    if(s+3<S) mm_load(Ah,Al,Bh,Bl,sb,tid,row0,col0,K,s+3);
    CP_COMMIT();
  }

  #pragma unroll
  for(int mi=0;mi<4;mi++){
    #pragma unroll
    for(int h=0;h<2;h++){
      const int grow=row0+m0+mi*16+(lane>>2)+h*8;
      #pragma unroll
      for(int nj=0;nj<4;nj++){
        const int gcol=col0+n0+nj*8+2*(lane&3);
        const float v0=acc[mi][nj][2*h], v1=acc[mi][nj][2*h+1];
        if(EPI==1){
          float2 rv=*(const float2*)(R+(size_t)grow*N+gcol);
          *(float2*)(Cf+(size_t)grow*N+gcol)=make_float2(v0+rv.x, v1+rv.y);
        } else {
          float a=v0,b=v1;
          if(EPI==3){ a*=SCALEC; b*=SCALEC; }
          uint32_t lo, hi=pack2(a,b,lo);
          *(uint32_t*)(Ch+(size_t)grow*N+gcol)=hi;
          *(uint32_t*)(Cl+(size_t)grow*N+gcol)=lo;
        }
      }
    }
  }
}

// ---------------- fp16 2-pass GEMM (FFN): C = A[M,K] @ (32*W)t[N,K]^T / 32 ----------------
// stage (48KB): A@0 (16KB), Bh@16384, Bl@32768
#define MM2_STAGE 49152
#define MM2_SMEM  (3*MM2_STAGE)

__device__ __forceinline__ void mm2_load(const __half* A,const __half* Bh,const __half* Bl,
    uint32_t sb,int tid,int row0,int col0,int K,int s){
  const int k0=s*64; const uint32_t st=sb+(s%3)*MM2_STAGE;
  #pragma unroll
  for(int i=0;i<4;i++){
    int id=tid+256*i; uint32_t r=id>>3, c=id&7; uint32_t so=soff(r,c);
    cp16(st+so,       A +(size_t)(row0+r)*K+k0+c*8);
    cp16(st+16384+so, Bh+(size_t)(col0+r)*K+k0+c*8);
    cp16(st+32768+so, Bl+(size_t)(col0+r)*K+k0+c*8);
  }
}

// EPI: 0 = gelu -> fp16 single, 1 = +residual -> fp32
template <int EPI>
__global__ void __launch_bounds__(256,1) mm2_kernel(const __half* __restrict__ A,
    const __half* __restrict__ Bh,const __half* __restrict__ Bl,
    const float* __restrict__ R, float* __restrict__ Cf,
    __half* __restrict__ Ch, int N, int K){
  extern __shared__ char smc[];
  const uint32_t sb=smem_u32(smc);
  const int tid=threadIdx.x, wid=tid>>5, lane=tid&31;
  const int row0=blockIdx.y*128, col0=blockIdx.x*128;
  const int m0=(wid>>2)*64, n0=(wid&3)*32;

  float acc[4][4][4];
  #pragma unroll
  for(int i=0;i<4;i++)
    #pragma unroll
    for(int j=0;j<4;j++)
      #pragma unroll
      for(int k=0;k<4;k++) acc[i][j][k]=0.f;

  const int S=K/64;
  mm2_load(A,Bh,Bl,sb,tid,row0,col0,K,0); CP_COMMIT();
  mm2_load(A,Bh,Bl,sb,tid,row0,col0,K,1); CP_COMMIT();
  mm2_load(A,Bh,Bl,sb,tid,row0,col0,K,2); CP_COMMIT();

  for(int s=0;s<S;s++){
    CP_WAIT2();
    __syncthreads();
    const uint32_t st=sb+(s%3)*MM2_STAGE;
    #pragma unroll
    for(int kk=0;kk<4;kk++){
      const uint32_t chk=kk*2+(lane>>4);
      uint32_t bh[2][4], bl[2][4];
      #pragma unroll
      for(int ni=0;ni<2;ni++){
        const uint32_t r=n0+ni*16+(lane&15);
        const uint32_t o=soff(r,chk);
        ldsm4(bh[ni], st+16384+o);
        ldsm4(bl[ni], st+32768+o);
      }
      #pragma unroll
      for(int mi=0;mi<4;mi++){
        const uint32_t r=m0+mi*16+(lane&15);
        const uint32_t o=soff(r,chk);
        uint32_t a[4];
        ldsm4(a, st+o);
        #pragma unroll
        for(int nj=0;nj<4;nj++){
          const uint32_t b0h=bh[nj>>1][nj&1], b1h=bh[nj>>1][(nj&1)+2];
          const uint32_t b0l=bl[nj>>1][nj&1], b1l=bl[nj>>1][(nj&1)+2];
          mma16816h(acc[mi][nj], a, b0h, b1h);
          mma16816h(acc[mi][nj], a, b0l, b1l);
        }
      }
    }
    __syncthreads();
    if(s+3<S) mm2_load(A,Bh,Bl,sb,tid,row0,col0,K,s+3);
    CP_COMMIT();
  }

  #pragma unroll
  for(int mi=0;mi<4;mi++){
    #pragma unroll
    for(int h=0;h<2;h++){
      const int grow=row0+m0+mi*16+(lane>>2)+h*8;
      #pragma unroll
      for(int nj=0;nj<4;nj++){
        const int gcol=col0+n0+nj*8+2*(lane&3);
        const float v0=acc[mi][nj][2*h]*0.03125f, v1=acc[mi][nj][2*h+1]*0.03125f;
        if(EPI==1){
          float2 rv=*(const float2*)(R+(size_t)grow*N+gcol);
          *(float2*)(Cf+(size_t)grow*N+gcol)=make_float2(v0+rv.x, v1+rv.y);
        } else {
          *(uint32_t*)(Ch+(size_t)grow*N+gcol)=packh(gelu_tanh(v0),gelu_tanh(v1));
        }
      }
    }
  }
}

// ---------------- FA2 attention (bf16 3-pass HMMA), 128 threads, 2 CTAs/SM ----------------
#define AT_SMEM 98304

__device__ __forceinline__ void attn_loadkv(const bf16* KVh,const bf16* KVl,
    uint32_t sb,int tid,size_t kr0,int h,int buf){
  const uint32_t st=sb+32768+buf*32768;
  #pragma unroll
  for(int i=0;i<4;i++){
    int id=tid+128*i; uint32_t r=id>>3, c=id&7; uint32_t so=soff(r,c);
    const size_t g=(kr0+r)*2048 + (size_t)h*64 + c*8;
    cp16(st+so,        KVh+g);
    cp16(st+8192+so,   KVl+g);
    cp16(st+16384+so,  KVh+g+1024);
    cp16(st+24576+so,  KVl+g+1024);
  }
}

__global__ void __launch_bounds__(128,2) attn_kernel(const bf16* __restrict__ Qh,const bf16* __restrict__ Ql,
    const bf16* __restrict__ KVh,const bf16* __restrict__ KVl,
    bf16* __restrict__ Ch, bf16* __restrict__ Cl){
  extern __shared__ char smc[];
  const uint32_t sb=smem_u32(smc);
  const int tid=threadIdx.x, wid=tid>>5, lane=tid&31;
  const int qt=blockIdx.x, h=blockIdx.y, b=blockIdx.z;
  const size_t qrow0=(size_t)(b*QL+qt*128);

  #pragma unroll
  for(int i=0;i<8;i++){
    int id=tid+128*i; uint32_t r=id>>3, c=id&7; uint32_t so=soff(r,c);
    const size_t g=(qrow0+r)*DIM + (size_t)h*64 + c*8;
    cp16(sb+so,       Qh+g);
    cp16(sb+16384+so, Ql+g);
  }
  attn_loadkv(KVh,KVl,sb,tid,(size_t)b*KL,h,0); CP_COMMIT();
  attn_loadkv(KVh,KVl,sb,tid,(size_t)b*KL+64,h,1); CP_COMMIT();

  float O[2][8][4];
  #pragma unroll
  for(int i=0;i<2;i++)
    #pragma unroll
    for(int j=0;j<8;j++)
      #pragma unroll
      for(int k=0;k<4;k++) O[i][j][k]=0.f;
  float mrun[2][2]={{-1e30f,-1e30f},{-1e30f,-1e30f}};
  float lrun[2][2]={{0.f,0.f},{0.f,0.f}};

  const int NT=KL/64;
  for(int t=0;t<NT;t++){
    if(t+1<NT) CP_WAIT1(); else CP_WAIT0();
    __syncthreads();
    const uint32_t st=sb+32768+(t&1)*32768;

    float S[2][8][4];
    #pragma unroll
    for(int i=0;i<2;i++)
      #pragma unroll
      for(int j=0;j<8;j++)
        #pragma unroll
        for(int k=0;k<4;k++) S[i][j][k]=0.f;
    #pragma unroll
    for(int kk=0;kk<4;kk++){
      const uint32_t chk=kk*2+(lane>>4);
      uint32_t qh[2][4], ql[2][4];
      #pragma unroll
      for(int mi=0;mi<2;mi++){
        const uint32_t r=wid*32+mi*16+(lane&15);
        const uint32_t o=soff(r,chk);
        ldsm4(qh[mi], sb+o);
        ldsm4(ql[mi], sb+16384+o);
      }
      #pragma unroll
      for(int nk=0;nk<4;nk++){
        const uint32_t r=nk*16+(lane&15);
        const uint32_t o=soff(r,chk);
        uint32_t kh[4], kl[4];
        ldsm4(kh, st+o);
        ldsm4(kl, st+8192+o);
        #pragma unroll
        for(int mi=0;mi<2;mi++){
          mma16816(S[mi][2*nk],   qh[mi], kh[0], kh[2]);
          mma16816(S[mi][2*nk+1], qh[mi], kh[1], kh[3]);
          mma16816(S[mi][2*nk],   qh[mi], kl[0], kl[2]);
          mma16816(S[mi][2*nk+1], qh[mi], kl[1], kl[3]);
          mma16816(S[mi][2*nk],   ql[mi], kh[0], kh[2]);
          mma16816(S[mi][2*nk+1], ql[mi], kh[1], kh[3]);
        }
      }
    }

    // ---- online softmax in exp2 domain (SCALEC folded into Q) ----
    float alpha[2][2];
    #pragma unroll
    for(int mi=0;mi<2;mi++)
      #pragma unroll
      for(int hh=0;hh<2;hh++){
        float mx=-1e30f;
        #pragma unroll
        for(int nj=0;nj<8;nj++){ mx=fmaxf(mx,S[mi][nj][2*hh]); mx=fmaxf(mx,S[mi][nj][2*hh+1]); }
        mx=fmaxf(mx,__shfl_xor_sync(~0u,mx,1));
        mx=fmaxf(mx,__shfl_xor_sync(~0u,mx,2));
        const float mn=fmaxf(mrun[mi][hh],mx);
        alpha[mi][hh]=ex2(mrun[mi][hh]-mn);
        mrun[mi][hh]=mn;
        float sum=0.f;
        #pragma unroll
        for(int nj=0;nj<8;nj++){
          float e0=ex2(S[mi][nj][2*hh]-mn), e1=ex2(S[mi][nj][2*hh+1]-mn);
          S[mi][nj][2*hh]=e0; S[mi][nj][2*hh+1]=e1; sum+=e0+e1;
        }
        sum+=__shfl_xor_sync(~0u,sum,1);
        sum+=__shfl_xor_sync(~0u,sum,2);
        lrun[mi][hh]=lrun[mi][hh]*alpha[mi][hh]+sum;
        #pragma unroll
        for(int nj=0;nj<8;nj++){
          O[mi][nj][2*hh]  *=alpha[mi][hh];
          O[mi][nj][2*hh+1]*=alpha[mi][hh];
        }
      }

    // ---- O += P @ V (3-pass), V via ldmatrix.trans ----
    #pragma unroll
    for(int ki=0;ki<4;ki++){
      uint32_t ph[2][4], pl[2][4];
      #pragma unroll
      for(int mi=0;mi<2;mi++){
        ph[mi][0]=pack2(S[mi][2*ki][0],  S[mi][2*ki][1],  pl[mi][0]);
        ph[mi][1]=pack2(S[mi][2*ki][2],  S[mi][2*ki][3],  pl[mi][1]);
        ph[mi][2]=pack2(S[mi][2*ki+1][0],S[mi][2*ki+1][1],pl[mi][2]);
        ph[mi][3]=pack2(S[mi][2*ki+1][2],S[mi][2*ki+1][3],pl[mi][3]);
      }
      #pragma unroll
      for(int nd=0;nd<4;nd++){
        const uint32_t r=ki*16+(lane&15);
        const uint32_t chk=nd*2+(lane>>4);
        const uint32_t o=soff(r,chk);
        uint32_t vh[4], vl[4];
        ldsm4t(vh, st+16384+o);
        ldsm4t(vl, st+24576+o);
        #pragma unroll
        for(int mi=0;mi<2;mi++){
          mma16816(O[mi][2*nd],   ph[mi], vh[0], vh[1]);
          mma16816(O[mi][2*nd+1], ph[mi], vh[2], vh[3]);
          mma16816(O[mi][2*nd],   ph[mi], vl[0], vl[1]);
          mma16816(O[mi][2*nd+1], ph[mi], vl[2], vl[3]);
          mma16816(O[mi][2*nd],   pl[mi], vh[0], vh[1]);
          mma16816(O[mi][2*nd+1], pl[mi], vh[2], vh[3]);
        }
      }
    }
    __syncthreads();
    if(t+2<NT){ attn_loadkv(KVh,KVl,sb,tid,(size_t)b*KL+(size_t)(t+2)*64,h,t&1); CP_COMMIT(); }
  }

  #pragma unroll
  for(int mi=0;mi<2;mi++)
    #pragma unroll
    for(int hh=0;hh<2;hh++){
      const float inv=1.f/lrun[mi][hh];
      const size_t grow=qrow0+wid*32+mi*16+(lane>>2)+hh*8;
      #pragma unroll
      for(int nj=0;nj<8;nj++){
        const int gcol=h*64+nj*8+2*(lane&3);
        uint32_t lo, hi=pack2(O[mi][nj][2*hh]*inv, O[mi][nj][2*hh+1]*inv, lo);
        *(uint32_t*)(Ch+grow*DIM+gcol)=hi;
        *(uint32_t*)(Cl+grow*DIM+gcol)=lo;
      }
    }
}

// ---------------- launch ----------------
extern "C" void kernel_launch(void* const* d_in, const int* in_sizes, int n_in,
                              void* d_out, int out_size){
  const float* q   =(const float*)d_in[0];
  const float* kv  =(const float*)d_in[1];
  const int*   ids =(const int*)  d_in[3];
  const float* ln1s=(const float*)d_in[4];
  const float* ln1b=(const float*)d_in[5];
  const float* Wq  =(const float*)d_in[6];
  const float* Wkv =(const float*)d_in[7];
  const float* Wo  =(const float*)d_in[8];
  const float* ln2s=(const float*)d_in[9];
  const float* ln2b=(const float*)d_in[10];
  const float* W1  =(const float*)d_in[11];
  const float* W2  =(const float*)d_in[12];
  const float* pe  =(const float*)d_in[13];
  float* out=(float*)d_out;

#define SYM(v,s) void* v##_; cudaGetSymbolAddress(&v##_,s);
  SYM(wqh,w_q_h) SYM(wql,w_q_l) SYM(wkvh,w_kv_h) SYM(wkvl,w_kv_l)
  SYM(woh,w_o_h) SYM(wol,w_o_l) SYM(w1h,w_1_h)   SYM(w1l,w_1_l)
  SYM(w2h,w_2_h) SYM(w2l,w_2_l)
  SYM(qlh,g_qln_h) SYM(qll,g_qln_l) SYM(kph,g_kvpe_h) SYM(kpl,g_kvpe_l)
  SYM(qph,g_qp_h)  SYM(qpl,g_qp_l)  SYM(kvph,g_kvp_h) SYM(kvpl,g_kvp_l)
  SYM(cth,g_ctx_h) SYM(ctl,g_ctx_l) SYM(atf,g_attn)
  SYM(hbuf,g_hb)   SYM(inbuf,g_in)
#undef SYM
#define BF(p) ((bf16*)p##_)
#define HF(p) ((__half*)p##_)
#define FL(p) ((float*)p##_)

  cudaFuncSetAttribute(mm_kernel<0>,  cudaFuncAttributeMaxDynamicSharedMemorySize, MM_SMEM);
  cudaFuncSetAttribute(mm_kernel<1>,  cudaFuncAttributeMaxDynamicSharedMemorySize, MM_SMEM);
  cudaFuncSetAttribute(mm_kernel<3>,  cudaFuncAttributeMaxDynamicSharedMemorySize, MM_SMEM);
  cudaFuncSetAttribute(mm2_kernel<0>, cudaFuncAttributeMaxDynamicSharedMemorySize, MM2_SMEM);
  cudaFuncSetAttribute(mm2_kernel<1>, cudaFuncAttributeMaxDynamicSharedMemorySize, MM2_SMEM);
  cudaFuncSetAttribute(attn_kernel,   cudaFuncAttributeMaxDynamicSharedMemorySize, AT_SMEM);

  dim3 tb(32,8);
  // launch order puts the two projection GEMMs at slots 5-6 for ncu (-s 5)
  tsplit_kernel<<<dim3(DIM/32,DIM/32),tb>>>(Wq, BF(wqh), BF(wql), DIM, DIM);      // 1
  ln_split_kernel<<<MQ,256>>>(q, ln1s, ln1b, BF(qlh), BF(qll));                    // 2
  kvpe_split_kernel<<<MKV,256>>>(kv, pe, ids, BF(kph), BF(kpl));                   // 3
  tsplit_kernel<<<dim3(2*DIM/32,DIM/32),tb>>>(Wkv,BF(wkvh),BF(wkvl),DIM, 2*DIM);   // 4
  mm_kernel<3><<<dim3(DIM/128,MQ/128),256,MM_SMEM>>>(BF(qlh),BF(qll),BF(wqh),BF(wql),
      nullptr,nullptr,BF(qph),BF(qpl),DIM,DIM);                                    // 5
  mm_kernel<0><<<dim3(2*DIM/128,MKV/128),256,MM_SMEM>>>(BF(kph),BF(kpl),BF(wkvh),BF(wkvl),
      nullptr,nullptr,BF(kvph),BF(kvpl),2*DIM,DIM);                                // 6
  tsplit_kernel<<<dim3(DIM/32,DIM/32),tb>>>(Wo, BF(woh), BF(wol), DIM, DIM);       // 7
  tsplit_h_kernel<<<dim3(INNER/32,DIM/32),tb>>>(W1, HF(w1h), HF(w1l), DIM, INNER); // 8
  tsplit_h_kernel<<<dim3(DIM/32,INNER/32),tb>>>(W2, HF(w2h), HF(w2l), INNER, DIM); // 9

  attn_kernel<<<dim3(QL/128,HEADS,BATCH),128,AT_SMEM>>>(BF(qph),BF(qpl),BF(kvph),BF(kvpl),
      BF(cth),BF(ctl));                                                            // 10

  mm_kernel<1><<<dim3(DIM/128,MQ/128),256,MM_SMEM>>>(BF(cth),BF(ctl),BF(woh),BF(wol),
      q,FL(atf),nullptr,nullptr,DIM,DIM);                                          // 11
  ln_half_kernel<<<MQ,256>>>(FL(atf), ln2s, ln2b, HF(hbuf));                       // 12
  mm2_kernel<0><<<dim3(INNER/128,MQ/128),256,MM2_SMEM>>>(HF(hbuf),HF(w1h),HF(w1l),
      nullptr,nullptr,HF(inbuf),INNER,DIM);                                        // 13
  mm2_kernel<1><<<dim3(DIM/128,MQ/128),256,MM2_SMEM>>>(HF(inbuf),HF(w2h),HF(w2l),
      FL(atf),out,nullptr,DIM,INNER);                                              // 14
}

// round 10
// speedup vs baseline: 1.7547x; 1.2722x over previous
#include <cuda_runtime.h>
#include <cuda_fp16.h>
#include <cstdint>
#include <math.h>

#define DIM    1024
#define HEADS  16
#define DH     64
#define BATCH  2
#define QL     1024
#define KL     4096
#define INNER  4096
#define MQ     (BATCH*QL)
#define MKV    (BATCH*KL)

// 0.125 * log2(e): folded into Q projection so softmax works in exp2 domain
#define SCALEC 0.18033688011112042f

// ---------------- scratch ----------------
#define ALN __align__(256)
__device__ ALN __half w_q_h [DIM*DIM],    w_q_l [DIM*DIM];     // fp16, pre-scaled x32
__device__ ALN __half w_kv_h[2*DIM*DIM],  w_kv_l[2*DIM*DIM];
__device__ ALN __half w_o_h [DIM*DIM],    w_o_l [DIM*DIM];
__device__ ALN __half w_1_h [INNER*DIM],  w_1_l [INNER*DIM];
__device__ ALN __half w_2_h [DIM*INNER],  w_2_l [DIM*INNER];
__device__ ALN __half g_qln [MQ*DIM];                           // fp16 single
__device__ ALN __half g_kvpe[MKV*DIM];                          // fp16 single
__device__ ALN __half g_qp  [MQ*DIM];                           // fp16 single (x SCALEC)
__device__ ALN __half g_kvp_h[MKV*2*DIM], g_kvp_l[MKV*2*DIM];   // fp16 hi/lo
__device__ ALN __half g_ctx [MQ*DIM];                           // fp16 single
__device__ ALN float  g_attn[MQ*DIM];
__device__ ALN __half g_hb  [MQ*DIM];
__device__ ALN __half g_in  [MQ*INNER];

// ---------------- PTX helpers (sm_80-compatible only) ----------------
__device__ __forceinline__ uint32_t smem_u32(const void* p){ uint32_t a;
  asm("{ .reg .u64 t; cvta.to.shared.u64 t, %1; cvt.u32.u64 %0, t; }":"=r"(a):"l"(p)); return a; }
__device__ __forceinline__ void cp16(uint32_t d, const void* s){
  asm volatile("cp.async.cg.shared.global [%0],[%1],16;"::"r"(d),"l"(s)); }
#define CP_COMMIT() asm volatile("cp.async.commit_group;":::"memory")
#define CP_WAIT0()  asm volatile("cp.async.wait_group 0;":::"memory")
#define CP_WAIT1()  asm volatile("cp.async.wait_group 1;":::"memory")
#define CP_WAIT2()  asm volatile("cp.async.wait_group 2;":::"memory")

__device__ __forceinline__ void ldsm4(uint32_t* r, uint32_t a){
  asm volatile("ldmatrix.sync.aligned.m8n8.x4.shared.b16 {%0,%1,%2,%3},[%4];"
    :"=r"(r[0]),"=r"(r[1]),"=r"(r[2]),"=r"(r[3]):"r"(a));
}
__device__ __forceinline__ void ldsm4t(uint32_t* r, uint32_t a){
  asm volatile("ldmatrix.sync.aligned.m8n8.x4.trans.shared.b16 {%0,%1,%2,%3},[%4];"
    :"=r"(r[0]),"=r"(r[1]),"=r"(r[2]),"=r"(r[3]):"r"(a));
}
// fp16 MMA, fp32 accumulate
__device__ __forceinline__ void mmah(float* d, const uint32_t* a, uint32_t b0, uint32_t b1){
  asm volatile("mma.sync.aligned.m16n8k16.row.col.f32.f16.f16.f32 "
    "{%0,%1,%2,%3},{%4,%5,%6,%7},{%8,%9},{%0,%1,%2,%3};"
    :"+f"(d[0]),"+f"(d[1]),"+f"(d[2]),"+f"(d[3])
    :"r"(a[0]),"r"(a[1]),"r"(a[2]),"r"(a[3]),"r"(b0),"r"(b1));
}
__device__ __forceinline__ uint32_t packh(float a, float b){
  __half2 h=__floats2half2_rn(a,b);
  return *(uint32_t*)&h;
}
__device__ __forceinline__ uint32_t packh_split(float a, float b, uint32_t& lo){
  __half ha=__float2half_rn(a), hb=__float2half_rn(b);
  __half la=__float2half_rn(a-__half2float(ha));
  __half lb=__float2half_rn(b-__half2float(hb));
  lo=(uint32_t)__half_as_ushort(la)|((uint32_t)__half_as_ushort(lb)<<16);
  return (uint32_t)__half_as_ushort(ha)|((uint32_t)__half_as_ushort(hb)<<16);
}
__device__ __forceinline__ float ex2(float x){
  float r; asm("ex2.approx.ftz.f32 %0,%1;":"=f"(r):"f"(x)); return r;
}
__device__ __forceinline__ float gelu_tanh(float x){
  return 0.5f*x*(1.0f+tanhf(0.7978845608028654f*(x+0.044715f*x*x*x)));
}
__device__ __forceinline__ uint32_t soff(uint32_t r, uint32_t ch){
  return r*128u + ((ch ^ (r & 7u)) << 4);
}

// ---------------- elementwise ----------------
// LN -> single fp16
__global__ void __launch_bounds__(256) ln_half_kernel(const float* __restrict__ x,
    const float* __restrict__ sc_, const float* __restrict__ bi_,
    __half* __restrict__ oh){
  const int row=blockIdx.x, t=threadIdx.x;
  const float4 v=((const float4*)(x+(size_t)row*DIM))[t];
  float s=v.x+v.y+v.z+v.w, ss=v.x*v.x+v.y*v.y+v.z*v.z+v.w*v.w;
  #pragma unroll
  for(int o=16;o;o>>=1){ s+=__shfl_xor_sync(~0u,s,o); ss+=__shfl_xor_sync(~0u,ss,o); }
  __shared__ float sm1[8], sm2[8];
  if((t&31)==0){ sm1[t>>5]=s; sm2[t>>5]=ss; }
  __syncthreads();
  float tot=0.f,tot2=0.f;
  #pragma unroll
  for(int i=0;i<8;i++){ tot+=sm1[i]; tot2+=sm2[i]; }
  const float mean=tot*(1.f/DIM), var=tot2*(1.f/DIM)-mean*mean, inv=rsqrtf(var+1e-6f);
  const float4 sc=((const float4*)sc_)[t], bi=((const float4*)bi_)[t];
  float o0=(v.x-mean)*inv*sc.x+bi.x, o1=(v.y-mean)*inv*sc.y+bi.y;
  float o2=(v.z-mean)*inv*sc.z+bi.z, o3=(v.w-mean)*inv*sc.w+bi.w;
  ((uint2*)(oh+(size_t)row*DIM))[t]=make_uint2(packh(o0,o1),packh(o2,o3));
}

// kv + pos_embed[ids] -> single fp16
__global__ void __launch_bounds__(256) kvpe_half_kernel(const float* __restrict__ kv,
    const float* __restrict__ pe, const int* __restrict__ ids,
    __half* __restrict__ oh){
  const int row=blockIdx.x, t=threadIdx.x;
  const int id=ids[row];
  float4 a=((const float4*)(kv+(size_t)row*DIM))[t];
  const float4 p=((const float4*)(pe+(size_t)id*DIM))[t];
  a.x+=p.x; a.y+=p.y; a.z+=p.z; a.w+=p.w;
  ((uint2*)(oh+(size_t)row*DIM))[t]=make_uint2(packh(a.x,a.y),packh(a.z,a.w));
}

// W[K,N] -> Wt[N,K] split hi/lo (fp16, scaled x32 so lo stays in normal range)
__global__ void __launch_bounds__(256) tsplit_h_kernel(const float* __restrict__ W,
    __half* __restrict__ Th, __half* __restrict__ Tl, int K, int N){
  __shared__ float t[32][33];
  const int tx=threadIdx.x, ty=threadIdx.y;
  const int bx=blockIdx.x*32, by=blockIdx.y*32;
  #pragma unroll
  for(int yy=ty;yy<32;yy+=8) t[yy][tx]=W[(size_t)(by+yy)*N+bx+tx];
  __syncthreads();
  #pragma unroll
  for(int yy=ty;yy<32;yy+=8){
    float v=t[tx][yy]*32.0f;
    __half h=__float2half_rn(v);
    __half l=__float2half_rn(v-__half2float(h));
    const size_t idx=(size_t)(bx+yy)*K+by+tx;
    Th[idx]=h; Tl[idx]=l;
  }
}

// ---------------- fp16 2-pass GEMM: C = A[M,K] @ (32*W)t[N,K]^T / 32 ----------------
// tile 128x128x64, 3-stage pipeline; stage (48KB): A@0 (16KB), Bh@16384, Bl@32768
#define MM2_STAGE 49152
#define MM2_SMEM  (3*MM2_STAGE)

__device__ __forceinline__ void mm2_load(const __half* A,const __half* Bh,const __half* Bl,
    uint32_t sb,int tid,int row0,int col0,int K,int s){
  const int k0=s*64; const uint32_t st=sb+(s%3)*MM2_STAGE;
  #pragma unroll
  for(int i=0;i<4;i++){
    int id=tid+256*i; uint32_t r=id>>3, c=id&7; uint32_t so=soff(r,c);
    cp16(st+so,       A +(size_t)(row0+r)*K+k0+c*8);
    cp16(st+16384+so, Bh+(size_t)(col0+r)*K+k0+c*8);
    cp16(st+32768+so, Bl+(size_t)(col0+r)*K+k0+c*8);
  }
}

// EPI: 0 = gelu -> fp16, 1 = +residual -> fp32, 2 = xSCALEC -> fp16, 3 = split fp16 hi/lo
template <int EPI>
__global__ void __launch_bounds__(256,1) mm2_kernel(const __half* __restrict__ A,
    const __half* __restrict__ Bh,const __half* __restrict__ Bl,
    const float* __restrict__ R, float* __restrict__ Cf,
    __half* __restrict__ Ch, __half* __restrict__ Cl, int N, int K){
  extern __shared__ char smc[];
  const uint32_t sb=smem_u32(smc);
  const int tid=threadIdx.x, wid=tid>>5, lane=tid&31;
  const int row0=blockIdx.y*128, col0=blockIdx.x*128;
  const int m0=(wid>>2)*64, n0=(wid&3)*32;

  float acc[4][4][4];
  #pragma unroll
  for(int i=0;i<4;i++)
    #pragma unroll
    for(int j=0;j<4;j++)
      #pragma unroll
      for(int k=0;k<4;k++) acc[i][j][k]=0.f;

  const int S=K/64;
  mm2_load(A,Bh,Bl,sb,tid,row0,col0,K,0); CP_COMMIT();
  mm2_load(A,Bh,Bl,sb,tid,row0,col0,K,1); CP_COMMIT();
  mm2_load(A,Bh,Bl,sb,tid,row0,col0,K,2); CP_COMMIT();

  for(int s=0;s<S;s++){
    CP_WAIT2();
    __syncthreads();
    const uint32_t st=sb+(s%3)*MM2_STAGE;
    #pragma unroll
    for(int kk=0;kk<4;kk++){
      const uint32_t chk=kk*2+(lane>>4);
      uint32_t bh[2][4], bl[2][4];
      #pragma unroll
      for(int ni=0;ni<2;ni++){
        const uint32_t r=n0+ni*16+(lane&15);
        const uint32_t o=soff(r,chk);
        ldsm4(bh[ni], st+16384+o);
        ldsm4(bl[ni], st+32768+o);
      }
      #pragma unroll
      for(int mi=0;mi<4;mi++){
        const uint32_t r=m0+mi*16+(lane&15);
        const uint32_t o=soff(r,chk);
        uint32_t a[4];
        ldsm4(a, st+o);
        #pragma unroll
        for(int nj=0;nj<4;nj++){
          const uint32_t b0h=bh[nj>>1][nj&1], b1h=bh[nj>>1][(nj&1)+2];
          const uint32_t b0l=bl[nj>>1][nj&1], b1l=bl[nj>>1][(nj&1)+2];
          mmah(acc[mi][nj], a, b0h, b1h);
          mmah(acc[mi][nj], a, b0l, b1l);
        }
      }
    }
    __syncthreads();
    if(s+3<S) mm2_load(A,Bh,Bl,sb,tid,row0,col0,K,s+3);
    CP_COMMIT();
  }

  #pragma unroll
  for(int mi=0;mi<4;mi++){
    #pragma unroll
    for(int h=0;h<2;h++){
      const int grow=row0+m0+mi*16+(lane>>2)+h*8;
      #pragma unroll
      for(int nj=0;nj<4;nj++){
        const int gcol=col0+n0+nj*8+2*(lane&3);
        const float v0=acc[mi][nj][2*h]*0.03125f, v1=acc[mi][nj][2*h+1]*0.03125f;
        if(EPI==1){
          float2 rv=*(const float2*)(R+(size_t)grow*N+gcol);
          *(float2*)(Cf+(size_t)grow*N+gcol)=make_float2(v0+rv.x, v1+rv.y);
        } else if(EPI==0){
          *(uint32_t*)(Ch+(size_t)grow*N+gcol)=packh(gelu_tanh(v0),gelu_tanh(v1));
        } else if(EPI==2){
          *(uint32_t*)(Ch+(size_t)grow*N+gcol)=packh(v0*SCALEC,v1*SCALEC);
        } else {
          uint32_t lo, hi=packh_split(v0,v1,lo);
          *(uint32_t*)(Ch+(size_t)grow*N+gcol)=hi;
          *(uint32_t*)(Cl+(size_t)grow*N+gcol)=lo;
        }
      }
    }
  }
}

// ---------------- FA2 attention (fp16 2-pass HMMA), 128 threads, 2 CTAs/SM ----------------
// smem: Q @0 (16KB, single fp16); stage buf @16384+buf*32768: Kh+0, Kl+8192, Vh+16384, Vl+24576
#define AT_SMEM 81920

__device__ __forceinline__ void attn_loadkv(const __half* KVh,const __half* KVl,
    uint32_t sb,int tid,size_t kr0,int h,int buf){
  const uint32_t st=sb+16384+buf*32768;
  #pragma unroll
  for(int i=0;i<4;i++){
    int id=tid+128*i; uint32_t r=id>>3, c=id&7; uint32_t so=soff(r,c);
    const size_t g=(kr0+r)*2048 + (size_t)h*64 + c*8;
    cp16(st+so,        KVh+g);
    cp16(st+8192+so,   KVl+g);
    cp16(st+16384+so,  KVh+g+1024);
    cp16(st+24576+so,  KVl+g+1024);
  }
}

__global__ void __launch_bounds__(128,2) attn_kernel(const __half* __restrict__ Q,
    const __half* __restrict__ KVh,const __half* __restrict__ KVl,
    __half* __restrict__ C){
  extern __shared__ char smc[];
  const uint32_t sb=smem_u32(smc);
  const int tid=threadIdx.x, wid=tid>>5, lane=tid&31;
  const int qt=blockIdx.x, h=blockIdx.y, b=blockIdx.z;
  const size_t qrow0=(size_t)(b*QL+qt*128);

  #pragma unroll
  for(int i=0;i<8;i++){
    int id=tid+128*i; uint32_t r=id>>3, c=id&7; uint32_t so=soff(r,c);
    cp16(sb+so, Q+(qrow0+r)*DIM + (size_t)h*64 + c*8);
  }
  attn_loadkv(KVh,KVl,sb,tid,(size_t)b*KL,h,0); CP_COMMIT();
  attn_loadkv(KVh,KVl,sb,tid,(size_t)b*KL+64,h,1); CP_COMMIT();

  float O[2][8][4];
  #pragma unroll
  for(int i=0;i<2;i++)
    #pragma unroll
    for(int j=0;j<8;j++)
      #pragma unroll
      for(int k=0;k<4;k++) O[i][j][k]=0.f;
  float mrun[2][2]={{-1e30f,-1e30f},{-1e30f,-1e30f}};
  float lrun[2][2]={{0.f,0.f},{0.f,0.f}};

  const int NT=KL/64;
  for(int t=0;t<NT;t++){
    if(t+1<NT) CP_WAIT1(); else CP_WAIT0();
    __syncthreads();
    const uint32_t st=sb+16384+(t&1)*32768;

    // ---- S = Q @ K^T (2-pass: Q single, K hi/lo) ----
    float S[2][8][4];
    #pragma unroll
    for(int i=0;i<2;i++)
      #pragma unroll
      for(int j=0;j<8;j++)
        #pragma unroll
        for(int k=0;k<4;k++) S[i][j][k]=0.f;
    #pragma unroll
    for(int kk=0;kk<4;kk++){
      const uint32_t chk=kk*2+(lane>>4);
      uint32_t q[2][4];
      #pragma unroll
      for(int mi=0;mi<2;mi++){
        const uint32_t r=wid*32+mi*16+(lane&15);
        ldsm4(q[mi], sb+soff(r,chk));
      }
      #pragma unroll
      for(int nk=0;nk<4;nk++){
        const uint32_t r=nk*16+(lane&15);
        const uint32_t o=soff(r,chk);
        uint32_t kh[4], kl[4];
        ldsm4(kh, st+o);
        ldsm4(kl, st+8192+o);
        #pragma unroll
        for(int mi=0;mi<2;mi++){
          mmah(S[mi][2*nk],   q[mi], kh[0], kh[2]);
          mmah(S[mi][2*nk+1], q[mi], kh[1], kh[3]);
          mmah(S[mi][2*nk],   q[mi], kl[0], kl[2]);
          mmah(S[mi][2*nk+1], q[mi], kl[1], kl[3]);
        }
      }
    }

    // ---- online softmax in exp2 domain (SCALEC folded into Q) ----
    float alpha[2][2];
    #pragma unroll
    for(int mi=0;mi<2;mi++)
      #pragma unroll
      for(int hh=0;hh<2;hh++){
        float mx=-1e30f;
        #pragma unroll
        for(int nj=0;nj<8;nj++){ mx=fmaxf(mx,S[mi][nj][2*hh]); mx=fmaxf(mx,S[mi][nj][2*hh+1]); }
        mx=fmaxf(mx,__shfl_xor_sync(~0u,mx,1));
        mx=fmaxf(mx,__shfl_xor_sync(~0u,mx,2));
        const float mn=fmaxf(mrun[mi][hh],mx);
        alpha[mi][hh]=ex2(mrun[mi][hh]-mn);
        mrun[mi][hh]=mn;
        float sum=0.f;
        #pragma unroll
        for(int nj=0;nj<8;nj++){
          float e0=ex2(S[mi][nj][2*hh]-mn), e1=ex2(S[mi][nj][2*hh+1]-mn);
          S[mi][nj][2*hh]=e0; S[mi][nj][2*hh+1]=e1; sum+=e0+e1;
        }
        sum+=__shfl_xor_sync(~0u,sum,1);
        sum+=__shfl_xor_sync(~0u,sum,2);
        lrun[mi][hh]=lrun[mi][hh]*alpha[mi][hh]+sum;
        #pragma unroll
        for(int nj=0;nj<8;nj++){
          O[mi][nj][2*hh]  *=alpha[mi][hh];
          O[mi][nj][2*hh+1]*=alpha[mi][hh];
        }
      }

    // ---- O += P @ V (2-pass: P single, V hi/lo), V via ldmatrix.trans ----
    #pragma unroll
    for(int ki=0;ki<4;ki++){
      uint32_t p[2][4];
      #pragma unroll
      for(int mi=0;mi<2;mi++){
        p[mi][0]=packh(S[mi][2*ki][0],  S[mi][2*ki][1]);
        p[mi][1]=packh(S[mi][2*ki][2],  S[mi][2*ki][3]);
        p[mi][2]=packh(S[mi][2*ki+1][0],S[mi][2*ki+1][1]);
        p[mi][3]=packh(S[mi][2*ki+1][2],S[mi][2*ki+1][3]);
      }
      #pragma unroll
      for(int nd=0;nd<4;nd++){
        const uint32_t r=ki*16+(lane&15);
        const uint32_t chk=nd*2+(lane>>4);
        const uint32_t o=soff(r,chk);
        uint32_t vh[4], vl[4];
        ldsm4t(vh, st+16384+o);
        ldsm4t(vl, st+24576+o);
        #pragma unroll
        for(int mi=0;mi<2;mi++){
          mmah(O[mi][2*nd],   p[mi], vh[0], vh[1]);
          mmah(O[mi][2*nd+1], p[mi], vh[2], vh[3]);
          mmah(O[mi][2*nd],   p[mi], vl[0], vl[1]);
          mmah(O[mi][2*nd+1], p[mi], vl[2], vl[3]);
        }
      }
    }
    __syncthreads();
    if(t+2<NT){ attn_loadkv(KVh,KVl,sb,tid,(size_t)b*KL+(size_t)(t+2)*64,h,t&1); CP_COMMIT(); }
  }

  #pragma unroll
  for(int mi=0;mi<2;mi++)
    #pragma unroll
    for(int hh=0;hh<2;hh++){
      const float inv=1.f/lrun[mi][hh];
      const size_t grow=qrow0+wid*32+mi*16+(lane>>2)+hh*8;
      #pragma unroll
      for(int nj=0;nj<8;nj++){
        const int gcol=h*64+nj*8+2*(lane&3);
        *(uint32_t*)(C+grow*DIM+gcol)=packh(O[mi][nj][2*hh]*inv, O[mi][nj][2*hh+1]*inv);
      }
    }
}

// ---------------- launch ----------------
extern "C" void kernel_launch(void* const* d_in, const int* in_sizes, int n_in,
                              void* d_out, int out_size){
  const float* q   =(const float*)d_in[0];
  const float* kv  =(const float*)d_in[1];
  const int*   ids =(const int*)  d_in[3];
  const float* ln1s=(const float*)d_in[4];
  const float* ln1b=(const float*)d_in[5];
  const float* Wq  =(const float*)d_in[6];
  const float* Wkv =(const float*)d_in[7];
  const float* Wo  =(const float*)d_in[8];
  const float* ln2s=(const float*)d_in[9];
  const float* ln2b=(const float*)d_in[10];
  const float* W1  =(const float*)d_in[11];
  const float* W2  =(const float*)d_in[12];
  const float* pe  =(const float*)d_in[13];
  float* out=(float*)d_out;

#define SYM(v,s) void* v##_; cudaGetSymbolAddress(&v##_,s);
  SYM(wqh,w_q_h) SYM(wql,w_q_l) SYM(wkvh,w_kv_h) SYM(wkvl,w_kv_l)
  SYM(woh,w_o_h) SYM(wol,w_o_l) SYM(w1h,w_1_h)   SYM(w1l,w_1_l)
  SYM(w2h,w_2_h) SYM(w2l,w_2_l)
  SYM(qln,g_qln) SYM(kpe,g_kvpe) SYM(qp,g_qp)
  SYM(kvph,g_kvp_h) SYM(kvpl,g_kvp_l)
  SYM(ctx,g_ctx) SYM(atf,g_attn) SYM(hbuf,g_hb) SYM(inbuf,g_in)
#undef SYM
#define HF(p) ((__half*)p##_)
#define FL(p) ((float*)p##_)

  cudaFuncSetAttribute(mm2_kernel<0>, cudaFuncAttributeMaxDynamicSharedMemorySize, MM2_SMEM);
  cudaFuncSetAttribute(mm2_kernel<1>, cudaFuncAttributeMaxDynamicSharedMemorySize, MM2_SMEM);
  cudaFuncSetAttribute(mm2_kernel<2>, cudaFuncAttributeMaxDynamicSharedMemorySize, MM2_SMEM);
  cudaFuncSetAttribute(mm2_kernel<3>, cudaFuncAttributeMaxDynamicSharedMemorySize, MM2_SMEM);
  cudaFuncSetAttribute(attn_kernel,   cudaFuncAttributeMaxDynamicSharedMemorySize, AT_SMEM);

  dim3 tb(32,8);
  // launch order keeps the two projection GEMMs at slots 5-6 for ncu (-s 5)
  tsplit_h_kernel<<<dim3(DIM/32,DIM/32),tb>>>(Wq, HF(wqh), HF(wql), DIM, DIM);        // 1
  ln_half_kernel<<<MQ,256>>>(q, ln1s, ln1b, HF(qln));                                  // 2
  kvpe_half_kernel<<<MKV,256>>>(kv, pe, ids, HF(kpe));                                 // 3
  tsplit_h_kernel<<<dim3(2*DIM/32,DIM/32),tb>>>(Wkv, HF(wkvh), HF(wkvl), DIM, 2*DIM);  // 4
  mm2_kernel<2><<<dim3(DIM/128,MQ/128),256,MM2_SMEM>>>(HF(qln),HF(wqh),HF(wql),
      nullptr,nullptr,HF(qp),nullptr,DIM,DIM);                                         // 5
  mm2_kernel<3><<<dim3(2*DIM/128,MKV/128),256,MM2_SMEM>>>(HF(kpe),HF(wkvh),HF(wkvl),
      nullptr,nullptr,HF(kvph),HF(kvpl),2*DIM,DIM);                                    // 6
  tsplit_h_kernel<<<dim3(DIM/32,DIM/32),tb>>>(Wo, HF(woh), HF(wol), DIM, DIM);         // 7
  tsplit_h_kernel<<<dim3(INNER/32,DIM/32),tb>>>(W1, HF(w1h), HF(w1l), DIM, INNER);     // 8
  tsplit_h_kernel<<<dim3(DIM/32,INNER/32),tb>>>(W2, HF(w2h), HF(w2l), INNER, DIM);     // 9

  attn_kernel<<<dim3(QL/128,HEADS,BATCH),128,AT_SMEM>>>(HF(qp),HF(kvph),HF(kvpl),
      HF(ctx));                                                                        // 10

  mm2_kernel<1><<<dim3(DIM/128,MQ/128),256,MM2_SMEM>>>(HF(ctx),HF(woh),HF(wol),
      q,FL(atf),nullptr,nullptr,DIM,DIM);                                              // 11
  ln_half_kernel<<<MQ,256>>>(FL(atf), ln2s, ln2b, HF(hbuf));                           // 12
  mm2_kernel<0><<<dim3(INNER/128,MQ/128),256,MM2_SMEM>>>(HF(hbuf),HF(w1h),HF(w1l),
      nullptr,nullptr,HF(inbuf),nullptr,INNER,DIM);                                    // 13
  mm2_kernel<1><<<dim3(DIM/128,MQ/128),256,MM2_SMEM>>>(HF(inbuf),HF(w2h),HF(w2l),
      FL(atf),out,nullptr,nullptr,DIM,INNER);                                          // 14
}

// round 11
// speedup vs baseline: 2.0885x; 1.1902x over previous
#include <cuda_runtime.h>
#include <cuda_fp16.h>
#include <cstdint>
#include <math.h>

#define DIM    1024
#define HEADS  16
#define DH     64
#define BATCH  2
#define QL     1024
#define KL     4096
#define INNER  4096
#define MQ     (BATCH*QL)
#define MKV    (BATCH*KL)

// 0.125 * log2(e): folded into Q projection so softmax works in exp2 domain
#define SCALEC 0.18033688011112042f

// ---------------- scratch ----------------
#define ALN __align__(256)
__device__ ALN __half w_q_h [DIM*DIM],    w_q_l [DIM*DIM];     // fp16, pre-scaled x32
__device__ ALN __half w_kv_h[2*DIM*DIM],  w_kv_l[2*DIM*DIM];
__device__ ALN __half w_o_h [DIM*DIM],    w_o_l [DIM*DIM];
__device__ ALN __half w_1_h [INNER*DIM],  w_1_l [INNER*DIM];
__device__ ALN __half w_2_h [DIM*INNER],  w_2_l [DIM*INNER];
__device__ ALN __half g_qln [MQ*DIM];                           // fp16 single
__device__ ALN __half g_kvpe[MKV*DIM];                          // fp16 single
__device__ ALN __half g_qp  [MQ*DIM];                           // fp16 single (x SCALEC)
__device__ ALN __half g_kvp [MKV*2*DIM];                        // fp16 single (K|V)
__device__ ALN __half g_ctx [MQ*DIM];                           // fp16 single
__device__ ALN float  g_attn[MQ*DIM];
__device__ ALN __half g_hb  [MQ*DIM];
__device__ ALN __half g_in  [MQ*INNER];

// ---------------- PTX helpers (sm_80-compatible only) ----------------
__device__ __forceinline__ uint32_t smem_u32(const void* p){ uint32_t a;
  asm("{ .reg .u64 t; cvta.to.shared.u64 t, %1; cvt.u32.u64 %0, t; }":"=r"(a):"l"(p)); return a; }
__device__ __forceinline__ void cp16(uint32_t d, const void* s){
  asm volatile("cp.async.cg.shared.global [%0],[%1],16;"::"r"(d),"l"(s)); }
#define CP_COMMIT() asm volatile("cp.async.commit_group;":::"memory")
#define CP_WAIT0()  asm volatile("cp.async.wait_group 0;":::"memory")
#define CP_WAIT1()  asm volatile("cp.async.wait_group 1;":::"memory")

__device__ __forceinline__ void ldsm4(uint32_t* r, uint32_t a){
  asm volatile("ldmatrix.sync.aligned.m8n8.x4.shared.b16 {%0,%1,%2,%3},[%4];"
    :"=r"(r[0]),"=r"(r[1]),"=r"(r[2]),"=r"(r[3]):"r"(a));
}
__device__ __forceinline__ void ldsm4t(uint32_t* r, uint32_t a){
  asm volatile("ldmatrix.sync.aligned.m8n8.x4.trans.shared.b16 {%0,%1,%2,%3},[%4];"
    :"=r"(r[0]),"=r"(r[1]),"=r"(r[2]),"=r"(r[3]):"r"(a));
}
// fp16 MMA, fp32 accumulate
__device__ __forceinline__ void mmah(float* d, const uint32_t* a, uint32_t b0, uint32_t b1){
  asm volatile("mma.sync.aligned.m16n8k16.row.col.f32.f16.f16.f32 "
    "{%0,%1,%2,%3},{%4,%5,%6,%7},{%8,%9},{%0,%1,%2,%3};"
    :"+f"(d[0]),"+f"(d[1]),"+f"(d[2]),"+f"(d[3])
    :"r"(a[0]),"r"(a[1]),"r"(a[2]),"r"(a[3]),"r"(b0),"r"(b1));
}
__device__ __forceinline__ uint32_t packh(float a, float b){
  __half2 h=__floats2half2_rn(a,b);
  return *(uint32_t*)&h;
}
__device__ __forceinline__ float ex2(float x){
  float r; asm("ex2.approx.ftz.f32 %0,%1;":"=f"(r):"f"(x)); return r;
}
__device__ __forceinline__ float gelu_tanh(float x){
  return 0.5f*x*(1.0f+tanhf(0.7978845608028654f*(x+0.044715f*x*x*x)));
}
__device__ __forceinline__ uint32_t soff(uint32_t r, uint32_t ch){
  return r*128u + ((ch ^ (r & 7u)) << 4);
}

// ---------------- elementwise ----------------
// LN -> single fp16
__global__ void __launch_bounds__(256) ln_half_kernel(const float* __restrict__ x,
    const float* __restrict__ sc_, const float* __restrict__ bi_,
    __half* __restrict__ oh){
  const int row=blockIdx.x, t=threadIdx.x;
  const float4 v=((const float4*)(x+(size_t)row*DIM))[t];
  float s=v.x+v.y+v.z+v.w, ss=v.x*v.x+v.y*v.y+v.z*v.z+v.w*v.w;
  #pragma unroll
  for(int o=16;o;o>>=1){ s+=__shfl_xor_sync(~0u,s,o); ss+=__shfl_xor_sync(~0u,ss,o); }
  __shared__ float sm1[8], sm2[8];
  if((t&31)==0){ sm1[t>>5]=s; sm2[t>>5]=ss; }
  __syncthreads();
  float tot=0.f,tot2=0.f;
  #pragma unroll
  for(int i=0;i<8;i++){ tot+=sm1[i]; tot2+=sm2[i]; }
  const float mean=tot*(1.f/DIM), var=tot2*(1.f/DIM)-mean*mean, inv=rsqrtf(var+1e-6f);
  const float4 sc=((const float4*)sc_)[t], bi=((const float4*)bi_)[t];
  float o0=(v.x-mean)*inv*sc.x+bi.x, o1=(v.y-mean)*inv*sc.y+bi.y;
  float o2=(v.z-mean)*inv*sc.z+bi.z, o3=(v.w-mean)*inv*sc.w+bi.w;
  ((uint2*)(oh+(size_t)row*DIM))[t]=make_uint2(packh(o0,o1),packh(o2,o3));
}

// kv + pos_embed[ids] -> single fp16
__global__ void __launch_bounds__(256) kvpe_half_kernel(const float* __restrict__ kv,
    const float* __restrict__ pe, const int* __restrict__ ids,
    __half* __restrict__ oh){
  const int row=blockIdx.x, t=threadIdx.x;
  const int id=ids[row];
  float4 a=((const float4*)(kv+(size_t)row*DIM))[t];
  const float4 p=((const float4*)(pe+(size_t)id*DIM))[t];
  a.x+=p.x; a.y+=p.y; a.z+=p.z; a.w+=p.w;
  ((uint2*)(oh+(size_t)row*DIM))[t]=make_uint2(packh(a.x,a.y),packh(a.z,a.w));
}

// W[K,N] -> Wt[N,K] split hi/lo (fp16, scaled x32 so lo stays in normal range)
__global__ void __launch_bounds__(256) tsplit_h_kernel(const float* __restrict__ W,
    __half* __restrict__ Th, __half* __restrict__ Tl, int K, int N){
  __shared__ float t[32][33];
  const int tx=threadIdx.x, ty=threadIdx.y;
  const int bx=blockIdx.x*32, by=blockIdx.y*32;
  #pragma unroll
  for(int yy=ty;yy<32;yy+=8) t[yy][tx]=W[(size_t)(by+yy)*N+bx+tx];
  __syncthreads();
  #pragma unroll
  for(int yy=ty;yy<32;yy+=8){
    float v=t[tx][yy]*32.0f;
    __half h=__float2half_rn(v);
    __half l=__float2half_rn(v-__half2float(h));
    const size_t idx=(size_t)(bx+yy)*K+by+tx;
    Th[idx]=h; Tl[idx]=l;
  }
}

// ---------------- fp16 2-pass GEMM: C = A[M,K] @ (32*W)t[N,K]^T / 32 ----------------
// tile 128x128x64, 2-stage pipeline, 2 CTAs/SM; stage (48KB): A@0 (16KB), Bh@16384, Bl@32768
#define MM2_STAGE 49152
#define MM2_SMEM  (2*MM2_STAGE)

__device__ __forceinline__ void mm2_load(const __half* A,const __half* Bh,const __half* Bl,
    uint32_t sb,int tid,int row0,int col0,int K,int s){
  const int k0=s*64; const uint32_t st=sb+(s&1)*MM2_STAGE;
  #pragma unroll
  for(int i=0;i<4;i++){
    int id=tid+256*i; uint32_t r=id>>3, c=id&7; uint32_t so=soff(r,c);
    cp16(st+so,       A +(size_t)(row0+r)*K+k0+c*8);
    cp16(st+16384+so, Bh+(size_t)(col0+r)*K+k0+c*8);
    cp16(st+32768+so, Bl+(size_t)(col0+r)*K+k0+c*8);
  }
}

// EPI: 0 = gelu -> fp16, 1 = +residual -> fp32, 2 = xSCALEC -> fp16, 4 = plain fp16
template <int EPI>
__global__ void __launch_bounds__(256,2) mm2_kernel(const __half* __restrict__ A,
    const __half* __restrict__ Bh,const __half* __restrict__ Bl,
    const float* __restrict__ R, float* __restrict__ Cf,
    __half* __restrict__ Ch, int N, int K){
  extern __shared__ char smc[];
  const uint32_t sb=smem_u32(smc);
  const int tid=threadIdx.x, wid=tid>>5, lane=tid&31;
  const int row0=blockIdx.y*128, col0=blockIdx.x*128;
  const int m0=(wid>>2)*64, n0=(wid&3)*32;

  float acc[4][4][4];
  #pragma unroll
  for(int i=0;i<4;i++)
    #pragma unroll
    for(int j=0;j<4;j++)
      #pragma unroll
      for(int k=0;k<4;k++) acc[i][j][k]=0.f;

  const int S=K/64;
  mm2_load(A,Bh,Bl,sb,tid,row0,col0,K,0); CP_COMMIT();
  mm2_load(A,Bh,Bl,sb,tid,row0,col0,K,1); CP_COMMIT();

  for(int s=0;s<S;s++){
    CP_WAIT1();
    __syncthreads();
    const uint32_t st=sb+(s&1)*MM2_STAGE;
    #pragma unroll
    for(int kk=0;kk<4;kk++){
      const uint32_t chk=kk*2+(lane>>4);
      uint32_t bh[2][4], bl[2][4];
      #pragma unroll
      for(int ni=0;ni<2;ni++){
        const uint32_t r=n0+ni*16+(lane&15);
        const uint32_t o=soff(r,chk);
        ldsm4(bh[ni], st+16384+o);
        ldsm4(bl[ni], st+32768+o);
      }
      #pragma unroll
      for(int mi=0;mi<4;mi++){
        const uint32_t r=m0+mi*16+(lane&15);
        uint32_t a[4];
        ldsm4(a, st+soff(r,chk));
        #pragma unroll
        for(int nj=0;nj<4;nj++){
          const uint32_t b0h=bh[nj>>1][nj&1], b1h=bh[nj>>1][(nj&1)+2];
          const uint32_t b0l=bl[nj>>1][nj&1], b1l=bl[nj>>1][(nj&1)+2];
          mmah(acc[mi][nj], a, b0h, b1h);
          mmah(acc[mi][nj], a, b0l, b1l);
        }
      }
    }
    __syncthreads();
    if(s+2<S) mm2_load(A,Bh,Bl,sb,tid,row0,col0,K,s+2);
    CP_COMMIT();
  }

  #pragma unroll
  for(int mi=0;mi<4;mi++){
    #pragma unroll
    for(int h=0;h<2;h++){
      const int grow=row0+m0+mi*16+(lane>>2)+h*8;
      #pragma unroll
      for(int nj=0;nj<4;nj++){
        const int gcol=col0+n0+nj*8+2*(lane&3);
        const float v0=acc[mi][nj][2*h]*0.03125f, v1=acc[mi][nj][2*h+1]*0.03125f;
        if(EPI==1){
          float2 rv=*(const float2*)(R+(size_t)grow*N+gcol);
          *(float2*)(Cf+(size_t)grow*N+gcol)=make_float2(v0+rv.x, v1+rv.y);
        } else if(EPI==0){
          *(uint32_t*)(Ch+(size_t)grow*N+gcol)=packh(gelu_tanh(v0),gelu_tanh(v1));
        } else if(EPI==2){
          *(uint32_t*)(Ch+(size_t)grow*N+gcol)=packh(v0*SCALEC,v1*SCALEC);
        } else {
          *(uint32_t*)(Ch+(size_t)grow*N+gcol)=packh(v0,v1);
        }
      }
    }
  }
}

// ---------------- FA2 attention (fp16 1-pass HMMA), 128 threads, 2 CTAs/SM ----------------
// smem: Q @0 (16KB); stage buf @16384+buf*16384: K@+0 (8KB), V@+8192 (8KB). total 48KB
#define AT_SMEM 49152

__device__ __forceinline__ void attn_loadkv(const __half* KV,
    uint32_t sb,int tid,size_t kr0,int h,int buf){
  const uint32_t st=sb+16384+buf*16384;
  #pragma unroll
  for(int i=0;i<4;i++){
    int id=tid+128*i; uint32_t r=id>>3, c=id&7; uint32_t so=soff(r,c);
    const size_t g=(kr0+r)*2048 + (size_t)h*64 + c*8;
    cp16(st+so,      KV+g);          // K
    cp16(st+8192+so, KV+g+1024);     // V
  }
}

__global__ void __launch_bounds__(128,2) attn_kernel(const __half* __restrict__ Q,
    const __half* __restrict__ KV, __half* __restrict__ C){
  extern __shared__ char smc[];
  const uint32_t sb=smem_u32(smc);
  const int tid=threadIdx.x, wid=tid>>5, lane=tid&31;
  const int qt=blockIdx.x, h=blockIdx.y, b=blockIdx.z;
  const size_t qrow0=(size_t)(b*QL+qt*128);

  #pragma unroll
  for(int i=0;i<8;i++){
    int id=tid+128*i; uint32_t r=id>>3, c=id&7; uint32_t so=soff(r,c);
    cp16(sb+so, Q+(qrow0+r)*DIM + (size_t)h*64 + c*8);
  }
  attn_loadkv(KV,sb,tid,(size_t)b*KL,h,0); CP_COMMIT();
  attn_loadkv(KV,sb,tid,(size_t)b*KL+64,h,1); CP_COMMIT();

  float O[2][8][4];
  #pragma unroll
  for(int i=0;i<2;i++)
    #pragma unroll
    for(int j=0;j<8;j++)
      #pragma unroll
      for(int k=0;k<4;k++) O[i][j][k]=0.f;
  float mrun[2][2]={{-1e30f,-1e30f},{-1e30f,-1e30f}};
  float lrun[2][2]={{0.f,0.f},{0.f,0.f}};

  const int NT=KL/64;
  for(int t=0;t<NT;t++){
    if(t+1<NT) CP_WAIT1(); else CP_WAIT0();
    __syncthreads();
    const uint32_t st=sb+16384+(t&1)*16384;

    // ---- S = Q @ K^T (1-pass fp16) ----
    float S[2][8][4];
    #pragma unroll
    for(int i=0;i<2;i++)
      #pragma unroll
      for(int j=0;j<8;j++)
        #pragma unroll
        for(int k=0;k<4;k++) S[i][j][k]=0.f;
    #pragma unroll
    for(int kk=0;kk<4;kk++){
      const uint32_t chk=kk*2+(lane>>4);
      uint32_t q[2][4];
      #pragma unroll
      for(int mi=0;mi<2;mi++){
        const uint32_t r=wid*32+mi*16+(lane&15);
        ldsm4(q[mi], sb+soff(r,chk));
      }
      #pragma unroll
      for(int nk=0;nk<4;nk++){
        const uint32_t r=nk*16+(lane&15);
        uint32_t kh[4];
        ldsm4(kh, st+soff(r,chk));
        #pragma unroll
        for(int mi=0;mi<2;mi++){
          mmah(S[mi][2*nk],   q[mi], kh[0], kh[2]);
          mmah(S[mi][2*nk+1], q[mi], kh[1], kh[3]);
        }
      }
    }

    // ---- online softmax in exp2 domain (SCALEC folded into Q) ----
    float alpha[2][2];
    #pragma unroll
    for(int mi=0;mi<2;mi++)
      #pragma unroll
      for(int hh=0;hh<2;hh++){
        float mx=-1e30f;
        #pragma unroll
        for(int nj=0;nj<8;nj++){ mx=fmaxf(mx,S[mi][nj][2*hh]); mx=fmaxf(mx,S[mi][nj][2*hh+1]); }
        mx=fmaxf(mx,__shfl_xor_sync(~0u,mx,1));
        mx=fmaxf(mx,__shfl_xor_sync(~0u,mx,2));
        const float mn=fmaxf(mrun[mi][hh],mx);
        alpha[mi][hh]=ex2(mrun[mi][hh]-mn);
        mrun[mi][hh]=mn;
        float sum=0.f;
        #pragma unroll
        for(int nj=0;nj<8;nj++){
          float e0=ex2(S[mi][nj][2*hh]-mn), e1=ex2(S[mi][nj][2*hh+1]-mn);
          S[mi][nj][2*hh]=e0; S[mi][nj][2*hh+1]=e1; sum+=e0+e1;
        }
        sum+=__shfl_xor_sync(~0u,sum,1);
        sum+=__shfl_xor_sync(~0u,sum,2);
        lrun[mi][hh]=lrun[mi][hh]*alpha[mi][hh]+sum;
        #pragma unroll
        for(int nj=0;nj<8;nj++){
          O[mi][nj][2*hh]  *=alpha[mi][hh];
          O[mi][nj][2*hh+1]*=alpha[mi][hh];
        }
      }

    // ---- O += P @ V (1-pass fp16), V via ldmatrix.trans ----
    #pragma unroll
    for(int ki=0;ki<4;ki++){
      uint32_t p[2][4];
      #pragma unroll
      for(int mi=0;mi<2;mi++){
        p[mi][0]=packh(S[mi][2*ki][0],  S[mi][2*ki][1]);
        p[mi][1]=packh(S[mi][2*ki][2],  S[mi][2*ki][3]);
        p[mi][2]=packh(S[mi][2*ki+1][0],S[mi][2*ki+1][1]);
        p[mi][3]=packh(S[mi][2*ki+1][2],S[mi][2*ki+1][3]);
      }
      #pragma unroll
      for(int nd=0;nd<4;nd++){
        const uint32_t r=ki*16+(lane&15);
        const uint32_t chk=nd*2+(lane>>4);
        uint32_t vh[4];
        ldsm4t(vh, st+8192+soff(r,chk));
        #pragma unroll
        for(int mi=0;mi<2;mi++){
          mmah(O[mi][2*nd],   p[mi], vh[0], vh[1]);
          mmah(O[mi][2*nd+1], p[mi], vh[2], vh[3]);
        }
      }
    }
    __syncthreads();
    if(t+2<NT){ attn_loadkv(KV,sb,tid,(size_t)b*KL+(size_t)(t+2)*64,h,t&1); CP_COMMIT(); }
  }

  #pragma unroll
  for(int mi=0;mi<2;mi++)
    #pragma unroll
    for(int hh=0;hh<2;hh++){
      const float inv=1.f/lrun[mi][hh];
      const size_t grow=qrow0+wid*32+mi*16+(lane>>2)+hh*8;
      #pragma unroll
      for(int nj=0;nj<8;nj++){
        const int gcol=h*64+nj*8+2*(lane&3);
        *(uint32_t*)(C+grow*DIM+gcol)=packh(O[mi][nj][2*hh]*inv, O[mi][nj][2*hh+1]*inv);
      }
    }
}

// ---------------- launch ----------------
extern "C" void kernel_launch(void* const* d_in, const int* in_sizes, int n_in,
                              void* d_out, int out_size){
  const float* q   =(const float*)d_in[0];
  const float* kv  =(const float*)d_in[1];
  const int*   ids =(const int*)  d_in[3];
  const float* ln1s=(const float*)d_in[4];
  const float* ln1b=(const float*)d_in[5];
  const float* Wq  =(const float*)d_in[6];
  const float* Wkv =(const float*)d_in[7];
  const float* Wo  =(const float*)d_in[8];
  const float* ln2s=(const float*)d_in[9];
  const float* ln2b=(const float*)d_in[10];
  const float* W1  =(const float*)d_in[11];
  const float* W2  =(const float*)d_in[12];
  const float* pe  =(const float*)d_in[13];
  float* out=(float*)d_out;

#define SYM(v,s) void* v##_; cudaGetSymbolAddress(&v##_,s);
  SYM(wqh,w_q_h) SYM(wql,w_q_l) SYM(wkvh,w_kv_h) SYM(wkvl,w_kv_l)
  SYM(woh,w_o_h) SYM(wol,w_o_l) SYM(w1h,w_1_h)   SYM(w1l,w_1_l)
  SYM(w2h,w_2_h) SYM(w2l,w_2_l)
  SYM(qln,g_qln) SYM(kpe,g_kvpe) SYM(qp,g_qp) SYM(kvp,g_kvp)
  SYM(ctx,g_ctx) SYM(atf,g_attn) SYM(hbuf,g_hb) SYM(inbuf,g_in)
#undef SYM
#define HF(p) ((__half*)p##_)
#define FL(p) ((float*)p##_)

  cudaFuncSetAttribute(mm2_kernel<0>, cudaFuncAttributeMaxDynamicSharedMemorySize, MM2_SMEM);
  cudaFuncSetAttribute(mm2_kernel<1>, cudaFuncAttributeMaxDynamicSharedMemorySize, MM2_SMEM);
  cudaFuncSetAttribute(mm2_kernel<2>, cudaFuncAttributeMaxDynamicSharedMemorySize, MM2_SMEM);
  cudaFuncSetAttribute(mm2_kernel<4>, cudaFuncAttributeMaxDynamicSharedMemorySize, MM2_SMEM);
  cudaFuncSetAttribute(attn_kernel,   cudaFuncAttributeMaxDynamicSharedMemorySize, AT_SMEM);

  dim3 tb(32,8);
  // launch order keeps the two projection GEMMs at slots 5-6 for ncu (-s 5)
  tsplit_h_kernel<<<dim3(DIM/32,DIM/32),tb>>>(Wq, HF(wqh), HF(wql), DIM, DIM);        // 1
  ln_half_kernel<<<MQ,256>>>(q, ln1s, ln1b, HF(qln));                                  // 2
  kvpe_half_kernel<<<MKV,256>>>(kv, pe, ids, HF(kpe));                                 // 3
  tsplit_h_kernel<<<dim3(2*DIM/32,DIM/32),tb>>>(Wkv, HF(wkvh), HF(wkvl), DIM, 2*DIM);  // 4
  mm2_kernel<2><<<dim3(DIM/128,MQ/128),256,MM2_SMEM>>>(HF(qln),HF(wqh),HF(wql),
      nullptr,nullptr,HF(qp),DIM,DIM);                                                 // 5
  mm2_kernel<4><<<dim3(2*DIM/128,MKV/128),256,MM2_SMEM>>>(HF(kpe),HF(wkvh),HF(wkvl),
      nullptr,nullptr,HF(kvp),2*DIM,DIM);                                              // 6
  tsplit_h_kernel<<<dim3(DIM/32,DIM/32),tb>>>(Wo, HF(woh), HF(wol), DIM, DIM);         // 7
  tsplit_h_kernel<<<dim3(INNER/32,DIM/32),tb>>>(W1, HF(w1h), HF(w1l), DIM, INNER);     // 8
  tsplit_h_kernel<<<dim3(DIM/32,INNER/32),tb>>>(W2, HF(w2h), HF(w2l), INNER, DIM);     // 9

  attn_kernel<<<dim3(QL/128,HEADS,BATCH),128,AT_SMEM>>>(HF(qp),HF(kvp),HF(ctx));       // 10

  mm2_kernel<1><<<dim3(DIM/128,MQ/128),256,MM2_SMEM>>>(HF(ctx),HF(woh),HF(wol),
      q,FL(atf),nullptr,DIM,DIM);                                                      // 11
  ln_half_kernel<<<MQ,256>>>(FL(atf), ln2s, ln2b, HF(hbuf));                           // 12
  mm2_kernel<0><<<dim3(INNER/128,MQ/128),256,MM2_SMEM>>>(HF(hbuf),HF(w1h),HF(w1l),
      nullptr,nullptr,HF(inbuf),INNER,DIM);                                            // 13
  mm2_kernel<1><<<dim3(DIM/128,MQ/128),256,MM2_SMEM>>>(HF(inbuf),HF(w2h),HF(w2l),
      FL(atf),out,nullptr,DIM,INNER);                                                  // 14
}

// round 12
// speedup vs baseline: 2.7596x; 1.3213x over previous
#include <cuda_runtime.h>
#include <cuda_fp16.h>
#include <cstdint>
#include <math.h>

#define DIM    1024
#define HEADS  16
#define DH     64
#define BATCH  2
#define QL     1024
#define KL     4096
#define INNER  4096
#define MQ     (BATCH*QL)
#define MKV    (BATCH*KL)

// 0.125 * log2(e): folded into Q projection so softmax works in exp2 domain
#define SCALEC 0.18033688011112042f

// ---------------- scratch ----------------
#define ALN __align__(256)
__device__ ALN __half w_q [DIM*DIM];                            // single fp16
__device__ ALN __half w_kv[2*DIM*DIM];                          // single fp16
__device__ ALN __half w_o [DIM*DIM];                            // single fp16
__device__ ALN __half w_1 [INNER*DIM];                          // single fp16
__device__ ALN __half w_2_h [DIM*INNER], w_2_l [DIM*INNER];     // fp16 hi/lo, x32
__device__ ALN __half g_qln [MQ*DIM];
__device__ ALN __half g_kvpe[MKV*DIM];
__device__ ALN __half g_qp  [MQ*DIM];                           // x SCALEC
__device__ ALN __half g_kvp [MKV*2*DIM];                        // K|V
__device__ ALN __half g_ctx [MQ*DIM];
__device__ ALN float  g_attn[MQ*DIM];
__device__ ALN __half g_hb  [MQ*DIM];
__device__ ALN __half g_in  [MQ*INNER];

// ---------------- PTX helpers (sm_80-compatible only) ----------------
__device__ __forceinline__ uint32_t smem_u32(const void* p){ uint32_t a;
  asm("{ .reg .u64 t; cvta.to.shared.u64 t, %1; cvt.u32.u64 %0, t; }":"=r"(a):"l"(p)); return a; }
__device__ __forceinline__ void cp16(uint32_t d, const void* s){
  asm volatile("cp.async.cg.shared.global [%0],[%1],16;"::"r"(d),"l"(s)); }
#define CP_COMMIT() asm volatile("cp.async.commit_group;":::"memory")
#define CP_WAIT0()  asm volatile("cp.async.wait_group 0;":::"memory")
#define CP_WAIT1()  asm volatile("cp.async.wait_group 1;":::"memory")

__device__ __forceinline__ void ldsm4(uint32_t* r, uint32_t a){
  asm volatile("ldmatrix.sync.aligned.m8n8.x4.shared.b16 {%0,%1,%2,%3},[%4];"
    :"=r"(r[0]),"=r"(r[1]),"=r"(r[2]),"=r"(r[3]):"r"(a));
}
__device__ __forceinline__ void ldsm4t(uint32_t* r, uint32_t a){
  asm volatile("ldmatrix.sync.aligned.m8n8.x4.trans.shared.b16 {%0,%1,%2,%3},[%4];"
    :"=r"(r[0]),"=r"(r[1]),"=r"(r[2]),"=r"(r[3]):"r"(a));
}
// fp16 MMA, fp32 accumulate
__device__ __forceinline__ void mmah(float* d, const uint32_t* a, uint32_t b0, uint32_t b1){
  asm volatile("mma.sync.aligned.m16n8k16.row.col.f32.f16.f16.f32 "
    "{%0,%1,%2,%3},{%4,%5,%6,%7},{%8,%9},{%0,%1,%2,%3};"
    :"+f"(d[0]),"+f"(d[1]),"+f"(d[2]),"+f"(d[3])
    :"r"(a[0]),"r"(a[1]),"r"(a[2]),"r"(a[3]),"r"(b0),"r"(b1));
}
__device__ __forceinline__ uint32_t packh(float a, float b){
  __half2 h=__floats2half2_rn(a,b);
  return *(uint32_t*)&h;
}
__device__ __forceinline__ float ex2(float x){
  float r; asm("ex2.approx.ftz.f32 %0,%1;":"=f"(r):"f"(x)); return r;
}
__device__ __forceinline__ float gelu_tanh(float x){
  return 0.5f*x*(1.0f+tanhf(0.7978845608028654f*(x+0.044715f*x*x*x)));
}
__device__ __forceinline__ uint32_t soff(uint32_t r, uint32_t ch){
  return r*128u + ((ch ^ (r & 7u)) << 4);
}

// ---------------- elementwise ----------------
__global__ void __launch_bounds__(256) ln_half_kernel(const float* __restrict__ x,
    const float* __restrict__ sc_, const float* __restrict__ bi_,
    __half* __restrict__ oh){
  const int row=blockIdx.x, t=threadIdx.x;
  const float4 v=((const float4*)(x+(size_t)row*DIM))[t];
  float s=v.x+v.y+v.z+v.w, ss=v.x*v.x+v.y*v.y+v.z*v.z+v.w*v.w;
  #pragma unroll
  for(int o=16;o;o>>=1){ s+=__shfl_xor_sync(~0u,s,o); ss+=__shfl_xor_sync(~0u,ss,o); }
  __shared__ float sm1[8], sm2[8];
  if((t&31)==0){ sm1[t>>5]=s; sm2[t>>5]=ss; }
  __syncthreads();
  float tot=0.f,tot2=0.f;
  #pragma unroll
  for(int i=0;i<8;i++){ tot+=sm1[i]; tot2+=sm2[i]; }
  const float mean=tot*(1.f/DIM), var=tot2*(1.f/DIM)-mean*mean, inv=rsqrtf(var+1e-6f);
  const float4 sc=((const float4*)sc_)[t], bi=((const float4*)bi_)[t];
  float o0=(v.x-mean)*inv*sc.x+bi.x, o1=(v.y-mean)*inv*sc.y+bi.y;
  float o2=(v.z-mean)*inv*sc.z+bi.z, o3=(v.w-mean)*inv*sc.w+bi.w;
  ((uint2*)(oh+(size_t)row*DIM))[t]=make_uint2(packh(o0,o1),packh(o2,o3));
}

__global__ void __launch_bounds__(256) kvpe_half_kernel(const float* __restrict__ kv,
    const float* __restrict__ pe, const int* __restrict__ ids,
    __half* __restrict__ oh){
  const int row=blockIdx.x, t=threadIdx.x;
  const int id=ids[row];
  float4 a=((const float4*)(kv+(size_t)row*DIM))[t];
  const float4 p=((const float4*)(pe+(size_t)id*DIM))[t];
  a.x+=p.x; a.y+=p.y; a.z+=p.z; a.w+=p.w;
  ((uint2*)(oh+(size_t)row*DIM))[t]=make_uint2(packh(a.x,a.y),packh(a.z,a.w));
}

// W[K,N] -> Wt[N,K] single fp16
__global__ void __launch_bounds__(256) tsplit1_kernel(const float* __restrict__ W,
    __half* __restrict__ Th, int K, int N){
  __shared__ float t[32][33];
  const int tx=threadIdx.x, ty=threadIdx.y;
  const int bx=blockIdx.x*32, by=blockIdx.y*32;
  #pragma unroll
  for(int yy=ty;yy<32;yy+=8) t[yy][tx]=W[(size_t)(by+yy)*N+bx+tx];
  __syncthreads();
  #pragma unroll
  for(int yy=ty;yy<32;yy+=8)
    Th[(size_t)(bx+yy)*K+by+tx]=__float2half_rn(t[tx][yy]);
}

// W[K,N] -> Wt[N,K] split hi/lo (fp16, scaled x32 so lo stays in normal range)
__global__ void __launch_bounds__(256) tsplit2_kernel(const float* __restrict__ W,
    __half* __restrict__ Th, __half* __restrict__ Tl, int K, int N){
  __shared__ float t[32][33];
  const int tx=threadIdx.x, ty=threadIdx.y;
  const int bx=blockIdx.x*32, by=blockIdx.y*32;
  #pragma unroll
  for(int yy=ty;yy<32;yy+=8) t[yy][tx]=W[(size_t)(by+yy)*N+bx+tx];
  __syncthreads();
  #pragma unroll
  for(int yy=ty;yy<32;yy+=8){
    float v=t[tx][yy]*32.0f;
    __half h=__float2half_rn(v);
    __half l=__float2half_rn(v-__half2float(h));
    const size_t idx=(size_t)(bx+yy)*K+by+tx;
    Th[idx]=h; Tl[idx]=l;
  }
}

// ---------------- fp16 1-pass GEMM: C = A[M,K] @ Wt[N,K]^T ----------------
// tile 128x128x64, 2-stage pipeline, 2 CTAs/SM; stage (32KB): A@0 (16KB), B@16384
#define MM1_STAGE 32768
#define MM1_SMEM  (2*MM1_STAGE)

__device__ __forceinline__ void mm1_load(const __half* A,const __half* B,
    uint32_t sb,int tid,int row0,int col0,int K,int s){
  const int k0=s*64; const uint32_t st=sb+(s&1)*MM1_STAGE;
  #pragma unroll
  for(int i=0;i<4;i++){
    int id=tid+256*i; uint32_t r=id>>3, c=id&7; uint32_t so=soff(r,c);
    cp16(st+so,       A+(size_t)(row0+r)*K+k0+c*8);
    cp16(st+16384+so, B+(size_t)(col0+r)*K+k0+c*8);
  }
}

// EPI: 0 = gelu -> fp16, 1 = +residual -> fp32, 2 = xSCALEC -> fp16, 4 = plain fp16
template <int EPI>
__global__ void __launch_bounds__(256,2) mm1_kernel(const __half* __restrict__ A,
    const __half* __restrict__ B,
    const float* __restrict__ R, float* __restrict__ Cf,
    __half* __restrict__ Ch, int N, int K){
  extern __shared__ char smc[];
  const uint32_t sb=smem_u32(smc);
  const int tid=threadIdx.x, wid=tid>>5, lane=tid&31;
  const int row0=blockIdx.y*128, col0=blockIdx.x*128;
  const int m0=(wid>>2)*64, n0=(wid&3)*32;

  float acc[4][4][4];
  #pragma unroll
  for(int i=0;i<4;i++)
    #pragma unroll
    for(int j=0;j<4;j++)
      #pragma unroll
      for(int k=0;k<4;k++) acc[i][j][k]=0.f;

  const int S=K/64;
  mm1_load(A,B,sb,tid,row0,col0,K,0); CP_COMMIT();
  mm1_load(A,B,sb,tid,row0,col0,K,1); CP_COMMIT();

  for(int s=0;s<S;s++){
    CP_WAIT1();
    __syncthreads();
    const uint32_t st=sb+(s&1)*MM1_STAGE;
    #pragma unroll
    for(int kk=0;kk<4;kk++){
      const uint32_t chk=kk*2+(lane>>4);
      uint32_t bh[2][4];
      #pragma unroll
      for(int ni=0;ni<2;ni++){
        const uint32_t r=n0+ni*16+(lane&15);
        ldsm4(bh[ni], st+16384+soff(r,chk));
      }
      #pragma unroll
      for(int mi=0;mi<4;mi++){
        const uint32_t r=m0+mi*16+(lane&15);
        uint32_t a[4];
        ldsm4(a, st+soff(r,chk));
        #pragma unroll
        for(int nj=0;nj<4;nj++)
          mmah(acc[mi][nj], a, bh[nj>>1][nj&1], bh[nj>>1][(nj&1)+2]);
      }
    }
    __syncthreads();
    if(s+2<S) mm1_load(A,B,sb,tid,row0,col0,K,s+2);
    CP_COMMIT();
  }

  #pragma unroll
  for(int mi=0;mi<4;mi++){
    #pragma unroll
    for(int h=0;h<2;h++){
      const int grow=row0+m0+mi*16+(lane>>2)+h*8;
      #pragma unroll
      for(int nj=0;nj<4;nj++){
        const int gcol=col0+n0+nj*8+2*(lane&3);
        const float v0=acc[mi][nj][2*h], v1=acc[mi][nj][2*h+1];
        if(EPI==1){
          float2 rv=*(const float2*)(R+(size_t)grow*N+gcol);
          *(float2*)(Cf+(size_t)grow*N+gcol)=make_float2(v0+rv.x, v1+rv.y);
        } else if(EPI==0){
          *(uint32_t*)(Ch+(size_t)grow*N+gcol)=packh(gelu_tanh(v0),gelu_tanh(v1));
        } else if(EPI==2){
          *(uint32_t*)(Ch+(size_t)grow*N+gcol)=packh(v0*SCALEC,v1*SCALEC);
        } else {
          *(uint32_t*)(Ch+(size_t)grow*N+gcol)=packh(v0,v1);
        }
      }
    }
  }
}

// ---------------- fp16 2-pass GEMM (W2 only): C = A @ (32*W)t^T / 32 + R ----------------
#define MM2_STAGE 49152
#define MM2_SMEM  (2*MM2_STAGE)

__device__ __forceinline__ void mm2_load(const __half* A,const __half* Bh,const __half* Bl,
    uint32_t sb,int tid,int row0,int col0,int K,int s){
  const int k0=s*64; const uint32_t st=sb+(s&1)*MM2_STAGE;
  #pragma unroll
  for(int i=0;i<4;i++){
    int id=tid+256*i; uint32_t r=id>>3, c=id&7; uint32_t so=soff(r,c);
    cp16(st+so,       A +(size_t)(row0+r)*K+k0+c*8);
    cp16(st+16384+so, Bh+(size_t)(col0+r)*K+k0+c*8);
    cp16(st+32768+so, Bl+(size_t)(col0+r)*K+k0+c*8);
  }
}

__global__ void __launch_bounds__(256,2) mm2_kernel(const __half* __restrict__ A,
    const __half* __restrict__ Bh,const __half* __restrict__ Bl,
    const float* __restrict__ R, float* __restrict__ Cf, int N, int K){
  extern __shared__ char smc[];
  const uint32_t sb=smem_u32(smc);
  const int tid=threadIdx.x, wid=tid>>5, lane=tid&31;
  const int row0=blockIdx.y*128, col0=blockIdx.x*128;
  const int m0=(wid>>2)*64, n0=(wid&3)*32;

  float acc[4][4][4];
  #pragma unroll
  for(int i=0;i<4;i++)
    #pragma unroll
    for(int j=0;j<4;j++)
      #pragma unroll
      for(int k=0;k<4;k++) acc[i][j][k]=0.f;

  const int S=K/64;
  mm2_load(A,Bh,Bl,sb,tid,row0,col0,K,0); CP_COMMIT();
  mm2_load(A,Bh,Bl,sb,tid,row0,col0,K,1); CP_COMMIT();

  for(int s=0;s<S;s++){
    CP_WAIT1();
    __syncthreads();
    const uint32_t st=sb+(s&1)*MM2_STAGE;
    #pragma unroll
    for(int kk=0;kk<4;kk++){
      const uint32_t chk=kk*2+(lane>>4);
      uint32_t bh[2][4], bl[2][4];
      #pragma unroll
      for(int ni=0;ni<2;ni++){
        const uint32_t r=n0+ni*16+(lane&15);
        const uint32_t o=soff(r,chk);
        ldsm4(bh[ni], st+16384+o);
        ldsm4(bl[ni], st+32768+o);
      }
      #pragma unroll
      for(int mi=0;mi<4;mi++){
        const uint32_t r=m0+mi*16+(lane&15);
        uint32_t a[4];
        ldsm4(a, st+soff(r,chk));
        #pragma unroll
        for(int nj=0;nj<4;nj++){
          mmah(acc[mi][nj], a, bh[nj>>1][nj&1], bh[nj>>1][(nj&1)+2]);
          mmah(acc[mi][nj], a, bl[nj>>1][nj&1], bl[nj>>1][(nj&1)+2]);
        }
      }
    }
    __syncthreads();
    if(s+2<S) mm2_load(A,Bh,Bl,sb,tid,row0,col0,K,s+2);
    CP_COMMIT();
  }

  #pragma unroll
  for(int mi=0;mi<4;mi++){
    #pragma unroll
    for(int h=0;h<2;h++){
      const int grow=row0+m0+mi*16+(lane>>2)+h*8;
      #pragma unroll
      for(int nj=0;nj<4;nj++){
        const int gcol=col0+n0+nj*8+2*(lane&3);
        const float v0=acc[mi][nj][2*h]*0.03125f, v1=acc[mi][nj][2*h+1]*0.03125f;
        float2 rv=*(const float2*)(R+(size_t)grow*N+gcol);
        *(float2*)(Cf+(size_t)grow*N+gcol)=make_float2(v0+rv.x, v1+rv.y);
      }
    }
  }
}

// ---------------- FA2 attention (fp16 1-pass HMMA), 128 threads, 2 CTAs/SM ----------------
#define AT_SMEM 49152

__device__ __forceinline__ void attn_loadkv(const __half* KV,
    uint32_t sb,int tid,size_t kr0,int h,int buf){
  const uint32_t st=sb+16384+buf*16384;
  #pragma unroll
  for(int i=0;i<4;i++){
    int id=tid+128*i; uint32_t r=id>>3, c=id&7; uint32_t so=soff(r,c);
    const size_t g=(kr0+r)*2048 + (size_t)h*64 + c*8;
    cp16(st+so,      KV+g);
    cp16(st+8192+so, KV+g+1024);
  }
}

__global__ void __launch_bounds__(128,2) attn_kernel(const __half* __restrict__ Q,
    const __half* __restrict__ KV, __half* __restrict__ C){
  extern __shared__ char smc[];
  const uint32_t sb=smem_u32(smc);
  const int tid=threadIdx.x, wid=tid>>5, lane=tid&31;
  const int qt=blockIdx.x, h=blockIdx.y, b=blockIdx.z;
  const size_t qrow0=(size_t)(b*QL+qt*128);

  #pragma unroll
  for(int i=0;i<8;i++){
    int id=tid+128*i; uint32_t r=id>>3, c=id&7; uint32_t so=soff(r,c);
    cp16(sb+so, Q+(qrow0+r)*DIM + (size_t)h*64 + c*8);
  }
  attn_loadkv(KV,sb,tid,(size_t)b*KL,h,0); CP_COMMIT();
  attn_loadkv(KV,sb,tid,(size_t)b*KL+64,h,1); CP_COMMIT();

  float O[2][8][4];
  #pragma unroll
  for(int i=0;i<2;i++)
    #pragma unroll
    for(int j=0;j<8;j++)
      #pragma unroll
      for(int k=0;k<4;k++) O[i][j][k]=0.f;
  float mrun[2][2]={{-1e30f,-1e30f},{-1e30f,-1e30f}};
  float lrun[2][2]={{0.f,0.f},{0.f,0.f}};

  const int NT=KL/64;
  for(int t=0;t<NT;t++){
    if(t+1<NT) CP_WAIT1(); else CP_WAIT0();
    __syncthreads();
    const uint32_t st=sb+16384+(t&1)*16384;

    float S[2][8][4];
    #pragma unroll
    for(int i=0;i<2;i++)
      #pragma unroll
      for(int j=0;j<8;j++)
        #pragma unroll
        for(int k=0;k<4;k++) S[i][j][k]=0.f;
    #pragma unroll
    for(int kk=0;kk<4;kk++){
      const uint32_t chk=kk*2+(lane>>4);
      uint32_t q[2][4];
      #pragma unroll
      for(int mi=0;mi<2;mi++){
        const uint32_t r=wid*32+mi*16+(lane&15);
        ldsm4(q[mi], sb+soff(r,chk));
      }
      #pragma unroll
      for(int nk=0;nk<4;nk++){
        const uint32_t r=nk*16+(lane&15);
        uint32_t kh[4];
        ldsm4(kh, st+soff(r,chk));
        #pragma unroll
        for(int mi=0;mi<2;mi++){
          mmah(S[mi][2*nk],   q[mi], kh[0], kh[2]);
          mmah(S[mi][2*nk+1], q[mi], kh[1], kh[3]);
        }
      }
    }

    float alpha[2][2];
    #pragma unroll
    for(int mi=0;mi<2;mi++)
      #pragma unroll
      for(int hh=0;hh<2;hh++){
        float mx=-1e30f;
        #pragma unroll
        for(int nj=0;nj<8;nj++){ mx=fmaxf(mx,S[mi][nj][2*hh]); mx=fmaxf(mx,S[mi][nj][2*hh+1]); }
        mx=fmaxf(mx,__shfl_xor_sync(~0u,mx,1));
        mx=fmaxf(mx,__shfl_xor_sync(~0u,mx,2));
        const float mn=fmaxf(mrun[mi][hh],mx);
        alpha[mi][hh]=ex2(mrun[mi][hh]-mn);
        mrun[mi][hh]=mn;
        float sum=0.f;
        #pragma unroll
        for(int nj=0;nj<8;nj++){
          float e0=ex2(S[mi][nj][2*hh]-mn), e1=ex2(S[mi][nj][2*hh+1]-mn);
          S[mi][nj][2*hh]=e0; S[mi][nj][2*hh+1]=e1; sum+=e0+e1;
        }
        sum+=__shfl_xor_sync(~0u,sum,1);
        sum+=__shfl_xor_sync(~0u,sum,2);
        lrun[mi][hh]=lrun[mi][hh]*alpha[mi][hh]+sum;
        #pragma unroll
        for(int nj=0;nj<8;nj++){
          O[mi][nj][2*hh]  *=alpha[mi][hh];
          O[mi][nj][2*hh+1]*=alpha[mi][hh];
        }
      }

    #pragma unroll
    for(int ki=0;ki<4;ki++){
      uint32_t p[2][4];
      #pragma unroll
      for(int mi=0;mi<2;mi++){
        p[mi][0]=packh(S[mi][2*ki][0],  S[mi][2*ki][1]);
        p[mi][1]=packh(S[mi][2*ki][2],  S[mi][2*ki][3]);
        p[mi][2]=packh(S[mi][2*ki+1][0],S[mi][2*ki+1][1]);
        p[mi][3]=packh(S[mi][2*ki+1][2],S[mi][2*ki+1][3]);
      }
      #pragma unroll
      for(int nd=0;nd<4;nd++){
        const uint32_t r=ki*16+(lane&15);
        const uint32_t chk=nd*2+(lane>>4);
        uint32_t vh[4];
        ldsm4t(vh, st+8192+soff(r,chk));
        #pragma unroll
        for(int mi=0;mi<2;mi++){
          mmah(O[mi][2*nd],   p[mi], vh[0], vh[1]);
          mmah(O[mi][2*nd+1], p[mi], vh[2], vh[3]);
        }
      }
    }
    __syncthreads();
    if(t+2<NT){ attn_loadkv(KV,sb,tid,(size_t)b*KL+(size_t)(t+2)*64,h,t&1); CP_COMMIT(); }
  }

  #pragma unroll
  for(int mi=0;mi<2;mi++)
    #pragma unroll
    for(int hh=0;hh<2;hh++){
      const float inv=1.f/lrun[mi][hh];
      const size_t grow=qrow0+wid*32+mi*16+(lane>>2)+hh*8;
      #pragma unroll
      for(int nj=0;nj<8;nj++){
        const int gcol=h*64+nj*8+2*(lane&3);
        *(uint32_t*)(C+grow*DIM+gcol)=packh(O[mi][nj][2*hh]*inv, O[mi][nj][2*hh+1]*inv);
      }
    }
}

// ---------------- launch ----------------
extern "C" void kernel_launch(void* const* d_in, const int* in_sizes, int n_in,
                              void* d_out, int out_size){
  const float* q   =(const float*)d_in[0];
  const float* kv  =(const float*)d_in[1];
  const int*   ids =(const int*)  d_in[3];
  const float* ln1s=(const float*)d_in[4];
  const float* ln1b=(const float*)d_in[5];
  const float* Wq  =(const float*)d_in[6];
  const float* Wkv =(const float*)d_in[7];
  const float* Wo  =(const float*)d_in[8];
  const float* ln2s=(const float*)d_in[9];
  const float* ln2b=(const float*)d_in[10];
  const float* W1  =(const float*)d_in[11];
  const float* W2  =(const float*)d_in[12];
  const float* pe  =(const float*)d_in[13];
  float* out=(float*)d_out;

#define SYM(v,s) void* v##_; cudaGetSymbolAddress(&v##_,s);
  SYM(wq,w_q) SYM(wkv,w_kv) SYM(wo,w_o) SYM(w1,w_1)
  SYM(w2h,w_2_h) SYM(w2l,w_2_l)
  SYM(qln,g_qln) SYM(kpe,g_kvpe) SYM(qp,g_qp) SYM(kvp,g_kvp)
  SYM(ctx,g_ctx) SYM(atf,g_attn) SYM(hbuf,g_hb) SYM(inbuf,g_in)
#undef SYM
#define HF(p) ((__half*)p##_)
#define FL(p) ((float*)p##_)

  cudaFuncSetAttribute(mm1_kernel<0>, cudaFuncAttributeMaxDynamicSharedMemorySize, MM1_SMEM);
  cudaFuncSetAttribute(mm1_kernel<1>, cudaFuncAttributeMaxDynamicSharedMemorySize, MM1_SMEM);
  cudaFuncSetAttribute(mm1_kernel<2>, cudaFuncAttributeMaxDynamicSharedMemorySize, MM1_SMEM);
  cudaFuncSetAttribute(mm1_kernel<4>, cudaFuncAttributeMaxDynamicSharedMemorySize, MM1_SMEM);
  cudaFuncSetAttribute(mm2_kernel,    cudaFuncAttributeMaxDynamicSharedMemorySize, MM2_SMEM);
  cudaFuncSetAttribute(attn_kernel,   cudaFuncAttributeMaxDynamicSharedMemorySize, AT_SMEM);

  dim3 tb(32,8);
  // ncu captures launch #4 -> put the biggest GEMM (kv-proj) there
  tsplit1_kernel<<<dim3(2*DIM/32,DIM/32),tb>>>(Wkv, HF(wkv), DIM, 2*DIM);            // 1
  kvpe_half_kernel<<<MKV,256>>>(kv, pe, ids, HF(kpe));                               // 2
  tsplit1_kernel<<<dim3(DIM/32,DIM/32),tb>>>(Wq, HF(wq), DIM, DIM);                  // 3
  mm1_kernel<4><<<dim3(2*DIM/128,MKV/128),256,MM1_SMEM>>>(HF(kpe),HF(wkv),
      nullptr,nullptr,HF(kvp),2*DIM,DIM);                                            // 4 (ncu)
  ln_half_kernel<<<MQ,256>>>(q, ln1s, ln1b, HF(qln));                                // 5
  mm1_kernel<2><<<dim3(DIM/128,MQ/128),256,MM1_SMEM>>>(HF(qln),HF(wq),
      nullptr,nullptr,HF(qp),DIM,DIM);                                               // 6
  tsplit1_kernel<<<dim3(DIM/32,DIM/32),tb>>>(Wo, HF(wo), DIM, DIM);                  // 7
  tsplit1_kernel<<<dim3(INNER/32,DIM/32),tb>>>(W1, HF(w1), DIM, INNER);              // 8
  tsplit2_kernel<<<dim3(DIM/32,INNER/32),tb>>>(W2, HF(w2h), HF(w2l), INNER, DIM);    // 9

  attn_kernel<<<dim3(QL/128,HEADS,BATCH),128,AT_SMEM>>>(HF(qp),HF(kvp),HF(ctx));     // 10

  mm1_kernel<1><<<dim3(DIM/128,MQ/128),256,MM1_SMEM>>>(HF(ctx),HF(wo),
      q,FL(atf),nullptr,DIM,DIM);                                                    // 11
  ln_half_kernel<<<MQ,256>>>(FL(atf), ln2s, ln2b, HF(hbuf));                         // 12
  mm1_kernel<0><<<dim3(INNER/128,MQ/128),256,MM1_SMEM>>>(HF(hbuf),HF(w1),
      nullptr,nullptr,HF(inbuf),INNER,DIM);                                          // 13
  mm2_kernel<<<dim3(DIM/128,MQ/128),256,MM2_SMEM>>>(HF(inbuf),HF(w2h),HF(w2l),
      FL(atf),out,DIM,INNER);                                                        // 14
}

// round 13
// speedup vs baseline: 3.1257x; 1.1327x over previous
#include <cuda_runtime.h>
#include <cuda_fp16.h>
#include <cstdint>
#include <math.h>

#define DIM    1024
#define HEADS  16
#define DH     64
#define BATCH  2
#define QL     1024
#define KL     4096
#define INNER  4096
#define MQ     (BATCH*QL)
#define MKV    (BATCH*KL)

// 0.125 * log2(e): folded into Q projection so softmax works in exp2 domain
#define SCALEC 0.18033688011112042f

// ---------------- scratch ----------------
#define ALN __align__(256)
__device__ ALN __half w_q [DIM*DIM];
__device__ ALN __half w_kv[2*DIM*DIM];
__device__ ALN __half w_o [DIM*DIM];
__device__ ALN __half w_1 [INNER*DIM];
__device__ ALN __half w_2 [DIM*INNER];
__device__ ALN __half g_qln [MQ*DIM];
__device__ ALN __half g_kvpe[MKV*DIM];
__device__ ALN __half g_qp  [MQ*DIM];                           // x SCALEC
__device__ ALN __half g_kvp [MKV*2*DIM];                        // K|V
__device__ ALN __half g_ctx [MQ*DIM];
__device__ ALN float  g_attn[MQ*DIM];
__device__ ALN __half g_hb  [MQ*DIM];
__device__ ALN __half g_in  [MQ*INNER];

// ---------------- PTX helpers (sm_80-compatible only) ----------------
__device__ __forceinline__ uint32_t smem_u32(const void* p){ uint32_t a;
  asm("{ .reg .u64 t; cvta.to.shared.u64 t, %1; cvt.u32.u64 %0, t; }":"=r"(a):"l"(p)); return a; }
__device__ __forceinline__ void cp16(uint32_t d, const void* s){
  asm volatile("cp.async.cg.shared.global [%0],[%1],16;"::"r"(d),"l"(s)); }
#define CP_COMMIT() asm volatile("cp.async.commit_group;":::"memory")
#define CP_WAIT0()  asm volatile("cp.async.wait_group 0;":::"memory")
#define CP_WAIT1()  asm volatile("cp.async.wait_group 1;":::"memory")

__device__ __forceinline__ void ldsm4(uint32_t* r, uint32_t a){
  asm volatile("ldmatrix.sync.aligned.m8n8.x4.shared.b16 {%0,%1,%2,%3},[%4];"
    :"=r"(r[0]),"=r"(r[1]),"=r"(r[2]),"=r"(r[3]):"r"(a));
}
__device__ __forceinline__ void ldsm4t(uint32_t* r, uint32_t a){
  asm volatile("ldmatrix.sync.aligned.m8n8.x4.trans.shared.b16 {%0,%1,%2,%3},[%4];"
    :"=r"(r[0]),"=r"(r[1]),"=r"(r[2]),"=r"(r[3]):"r"(a));
}
// fp16 MMA, fp32 accumulate
__device__ __forceinline__ void mmah(float* d, const uint32_t* a, uint32_t b0, uint32_t b1){
  asm volatile("mma.sync.aligned.m16n8k16.row.col.f32.f16.f16.f32 "
    "{%0,%1,%2,%3},{%4,%5,%6,%7},{%8,%9},{%0,%1,%2,%3};"
    :"+f"(d[0]),"+f"(d[1]),"+f"(d[2]),"+f"(d[3])
    :"r"(a[0]),"r"(a[1]),"r"(a[2]),"r"(a[3]),"r"(b0),"r"(b1));
}
__device__ __forceinline__ uint32_t packh(float a, float b){
  __half2 h=__floats2half2_rn(a,b);
  return *(uint32_t*)&h;
}
__device__ __forceinline__ float ex2(float x){
  float r; asm("ex2.approx.ftz.f32 %0,%1;":"=f"(r):"f"(x)); return r;
}
// gelu(x) = 0.5x(1+tanh(z)), z = 0.79788456(x + 0.044715 x^3)
//         = x * (1 - 1/(exp(2z)+1)), exp(2z) via ex2.approx
__device__ __forceinline__ float gelu_fast(float x){
  const float z = 0.7978845608028654f*(x + 0.044715f*x*x*x);
  const float e = ex2(z*2.8853900817779268f);   // exp(2z)
  float r; asm("rcp.approx.ftz.f32 %0,%1;":"=f"(r):"f"(e+1.0f));
  return x - x*r;
}
__device__ __forceinline__ uint32_t soff(uint32_t r, uint32_t ch){
  return r*128u + ((ch ^ (r & 7u)) << 4);
}

// ---------------- elementwise ----------------
__global__ void __launch_bounds__(256) ln_half_kernel(const float* __restrict__ x,
    const float* __restrict__ sc_, const float* __restrict__ bi_,
    __half* __restrict__ oh){
  const int row=blockIdx.x, t=threadIdx.x;
  const float4 v=((const float4*)(x+(size_t)row*DIM))[t];
  float s=v.x+v.y+v.z+v.w, ss=v.x*v.x+v.y*v.y+v.z*v.z+v.w*v.w;
  #pragma unroll
  for(int o=16;o;o>>=1){ s+=__shfl_xor_sync(~0u,s,o); ss+=__shfl_xor_sync(~0u,ss,o); }
  __shared__ float sm1[8], sm2[8];
  if((t&31)==0){ sm1[t>>5]=s; sm2[t>>5]=ss; }
  __syncthreads();
  float tot=0.f,tot2=0.f;
  #pragma unroll
  for(int i=0;i<8;i++){ tot+=sm1[i]; tot2+=sm2[i]; }
  const float mean=tot*(1.f/DIM), var=tot2*(1.f/DIM)-mean*mean, inv=rsqrtf(var+1e-6f);
  const float4 sc=((const float4*)sc_)[t], bi=((const float4*)bi_)[t];
  float o0=(v.x-mean)*inv*sc.x+bi.x, o1=(v.y-mean)*inv*sc.y+bi.y;
  float o2=(v.z-mean)*inv*sc.z+bi.z, o3=(v.w-mean)*inv*sc.w+bi.w;
  ((uint2*)(oh+(size_t)row*DIM))[t]=make_uint2(packh(o0,o1),packh(o2,o3));
}

__global__ void __launch_bounds__(256) kvpe_half_kernel(const float* __restrict__ kv,
    const float* __restrict__ pe, const int* __restrict__ ids,
    __half* __restrict__ oh){
  const int row=blockIdx.x, t=threadIdx.x;
  const int id=ids[row];
  float4 a=((const float4*)(kv+(size_t)row*DIM))[t];
  const float4 p=((const float4*)(pe+(size_t)id*DIM))[t];
  a.x+=p.x; a.y+=p.y; a.z+=p.z; a.w+=p.w;
  ((uint2*)(oh+(size_t)row*DIM))[t]=make_uint2(packh(a.x,a.y),packh(a.z,a.w));
}

// W[K,N] -> Wt[N,K] single fp16
__global__ void __launch_bounds__(256) tsplit1_kernel(const float* __restrict__ W,
    __half* __restrict__ Th, int K, int N){
  __shared__ float t[32][33];
  const int tx=threadIdx.x, ty=threadIdx.y;
  const int bx=blockIdx.x*32, by=blockIdx.y*32;
  #pragma unroll
  for(int yy=ty;yy<32;yy+=8) t[yy][tx]=W[(size_t)(by+yy)*N+bx+tx];
  __syncthreads();
  #pragma unroll
  for(int yy=ty;yy<32;yy+=8)
    Th[(size_t)(bx+yy)*K+by+tx]=__float2half_rn(t[tx][yy]);
}

// ---------------- fp16 1-pass GEMM: C = A[M,K] @ Wt[N,K]^T ----------------
// tile 128x128x64, 2-stage pipeline, 2 CTAs/SM; stage (32KB): A@0 (16KB), B@16384
#define MM1_STAGE 32768
#define MM1_SMEM  (2*MM1_STAGE)

__device__ __forceinline__ void mm1_load(const __half* A,const __half* B,
    uint32_t sb,int tid,int row0,int col0,int K,int s){
  const int k0=s*64; const uint32_t st=sb+(s&1)*MM1_STAGE;
  #pragma unroll
  for(int i=0;i<4;i++){
    int id=tid+256*i; uint32_t r=id>>3, c=id&7; uint32_t so=soff(r,c);
    cp16(st+so,       A+(size_t)(row0+r)*K+k0+c*8);
    cp16(st+16384+so, B+(size_t)(col0+r)*K+k0+c*8);
  }
}

// EPI: 0 = gelu -> fp16, 1 = +residual -> fp32, 2 = xSCALEC -> fp16, 4 = plain fp16
template <int EPI>
__global__ void __launch_bounds__(256,2) mm1_kernel(const __half* __restrict__ A,
    const __half* __restrict__ B,
    const float* __restrict__ R, float* __restrict__ Cf,
    __half* __restrict__ Ch, int N, int K){
  extern __shared__ char smc[];
  const uint32_t sb=smem_u32(smc);
  const int tid=threadIdx.x, wid=tid>>5, lane=tid&31;
  const int row0=blockIdx.y*128, col0=blockIdx.x*128;
  const int m0=(wid>>2)*64, n0=(wid&3)*32;

  float acc[4][4][4];
  #pragma unroll
  for(int i=0;i<4;i++)
    #pragma unroll
    for(int j=0;j<4;j++)
      #pragma unroll
      for(int k=0;k<4;k++) acc[i][j][k]=0.f;

  const int S=K/64;
  mm1_load(A,B,sb,tid,row0,col0,K,0); CP_COMMIT();
  mm1_load(A,B,sb,tid,row0,col0,K,1); CP_COMMIT();

  for(int s=0;s<S;s++){
    CP_WAIT1();
    __syncthreads();
    const uint32_t st=sb+(s&1)*MM1_STAGE;
    #pragma unroll
    for(int kk=0;kk<4;kk++){
      const uint32_t chk=kk*2+(lane>>4);
      uint32_t bh[2][4];
      #pragma unroll
      for(int ni=0;ni<2;ni++){
        const uint32_t r=n0+ni*16+(lane&15);
        ldsm4(bh[ni], st+16384+soff(r,chk));
      }
      #pragma unroll
      for(int mi=0;mi<4;mi++){
        const uint32_t r=m0+mi*16+(lane&15);
        uint32_t a[4];
        ldsm4(a, st+soff(r,chk));
        #pragma unroll
        for(int nj=0;nj<4;nj++)
          mmah(acc[mi][nj], a, bh[nj>>1][nj&1], bh[nj>>1][(nj&1)+2]);
      }
    }
    __syncthreads();
    if(s+2<S) mm1_load(A,B,sb,tid,row0,col0,K,s+2);
    CP_COMMIT();
  }

  #pragma unroll
  for(int mi=0;mi<4;mi++){
    #pragma unroll
    for(int h=0;h<2;h++){
      const int grow=row0+m0+mi*16+(lane>>2)+h*8;
      #pragma unroll
      for(int nj=0;nj<4;nj++){
        const int gcol=col0+n0+nj*8+2*(lane&3);
        const float v0=acc[mi][nj][2*h], v1=acc[mi][nj][2*h+1];
        if(EPI==1){
          float2 rv=*(const float2*)(R+(size_t)grow*N+gcol);
          *(float2*)(Cf+(size_t)grow*N+gcol)=make_float2(v0+rv.x, v1+rv.y);
        } else if(EPI==0){
          *(uint32_t*)(Ch+(size_t)grow*N+gcol)=packh(gelu_fast(v0),gelu_fast(v1));
        } else if(EPI==2){
          *(uint32_t*)(Ch+(size_t)grow*N+gcol)=packh(v0*SCALEC,v1*SCALEC);
        } else {
          *(uint32_t*)(Ch+(size_t)grow*N+gcol)=packh(v0,v1);
        }
      }
    }
  }
}

// ---------------- FA2 attention (fp16 1-pass HMMA), 128 threads, 2 CTAs/SM ----------------
#define AT_SMEM 49152

__device__ __forceinline__ void attn_loadkv(const __half* KV,
    uint32_t sb,int tid,size_t kr0,int h,int buf){
  const uint32_t st=sb+16384+buf*16384;
  #pragma unroll
  for(int i=0;i<4;i++){
    int id=tid+128*i; uint32_t r=id>>3, c=id&7; uint32_t so=soff(r,c);
    const size_t g=(kr0+r)*2048 + (size_t)h*64 + c*8;
    cp16(st+so,      KV+g);
    cp16(st+8192+so, KV+g+1024);
  }
}

__global__ void __launch_bounds__(128,2) attn_kernel(const __half* __restrict__ Q,
    const __half* __restrict__ KV, __half* __restrict__ C){
  extern __shared__ char smc[];
  const uint32_t sb=smem_u32(smc);
  const int tid=threadIdx.x, wid=tid>>5, lane=tid&31;
  const int qt=blockIdx.x, h=blockIdx.y, b=blockIdx.z;
  const size_t qrow0=(size_t)(b*QL+qt*128);

  #pragma unroll
  for(int i=0;i<8;i++){
    int id=tid+128*i; uint32_t r=id>>3, c=id&7; uint32_t so=soff(r,c);
    cp16(sb+so, Q+(qrow0+r)*DIM + (size_t)h*64 + c*8);
  }
  attn_loadkv(KV,sb,tid,(size_t)b*KL,h,0); CP_COMMIT();
  attn_loadkv(KV,sb,tid,(size_t)b*KL+64,h,1); CP_COMMIT();

  float O[2][8][4];
  #pragma unroll
  for(int i=0;i<2;i++)
    #pragma unroll
    for(int j=0;j<8;j++)
      #pragma unroll
      for(int k=0;k<4;k++) O[i][j][k]=0.f;
  float mrun[2][2]={{-1e30f,-1e30f},{-1e30f,-1e30f}};
  float lrun[2][2]={{0.f,0.f},{0.f,0.f}};

  const int NT=KL/64;
  for(int t=0;t<NT;t++){
    if(t+1<NT) CP_WAIT1(); else CP_WAIT0();
    __syncthreads();
    const uint32_t st=sb+16384+(t&1)*16384;

    float S[2][8][4];
    #pragma unroll
    for(int i=0;i<2;i++)
      #pragma unroll
      for(int j=0;j<8;j++)
        #pragma unroll
        for(int k=0;k<4;k++) S[i][j][k]=0.f;
    #pragma unroll
    for(int kk=0;kk<4;kk++){
      const uint32_t chk=kk*2+(lane>>4);
      uint32_t q[2][4];
      #pragma unroll
      for(int mi=0;mi<2;mi++){
        const uint32_t r=wid*32+mi*16+(lane&15);
        ldsm4(q[mi], sb+soff(r,chk));
      }
      #pragma unroll
      for(int nk=0;nk<4;nk++){
        const uint32_t r=nk*16+(lane&15);
        uint32_t kh[4];
        ldsm4(kh, st+soff(r,chk));
        #pragma unroll
        for(int mi=0;mi<2;mi++){
          mmah(S[mi][2*nk],   q[mi], kh[0], kh[2]);
          mmah(S[mi][2*nk+1], q[mi], kh[1], kh[3]);
        }
      }
    }

    float alpha[2][2];
    #pragma unroll
    for(int mi=0;mi<2;mi++)
      #pragma unroll
      for(int hh=0;hh<2;hh++){
        float mx=-1e30f;
        #pragma unroll
        for(int nj=0;nj<8;nj++){ mx=fmaxf(mx,S[mi][nj][2*hh]); mx=fmaxf(mx,S[mi][nj][2*hh+1]); }
        mx=fmaxf(mx,__shfl_xor_sync(~0u,mx,1));
        mx=fmaxf(mx,__shfl_xor_sync(~0u,mx,2));
        const float mn=fmaxf(mrun[mi][hh],mx);
        alpha[mi][hh]=ex2(mrun[mi][hh]-mn);
        mrun[mi][hh]=mn;
        float sum=0.f;
        #pragma unroll
        for(int nj=0;nj<8;nj++){
          float e0=ex2(S[mi][nj][2*hh]-mn), e1=ex2(S[mi][nj][2*hh+1]-mn);
          S[mi][nj][2*hh]=e0; S[mi][nj][2*hh+1]=e1; sum+=e0+e1;
        }
        sum+=__shfl_xor_sync(~0u,sum,1);
        sum+=__shfl_xor_sync(~0u,sum,2);
        lrun[mi][hh]=lrun[mi][hh]*alpha[mi][hh]+sum;
        #pragma unroll
        for(int nj=0;nj<8;nj++){
          O[mi][nj][2*hh]  *=alpha[mi][hh];
          O[mi][nj][2*hh+1]*=alpha[mi][hh];
        }
      }

    #pragma unroll
    for(int ki=0;ki<4;ki++){
      uint32_t p[2][4];
      #pragma unroll
      for(int mi=0;mi<2;mi++){
        p[mi][0]=packh(S[mi][2*ki][0],  S[mi][2*ki][1]);
        p[mi][1]=packh(S[mi][2*ki][2],  S[mi][2*ki][3]);
        p[mi][2]=packh(S[mi][2*ki+1][0],S[mi][2*ki+1][1]);
        p[mi][3]=packh(S[mi][2*ki+1][2],S[mi][2*ki+1][3]);
      }
      #pragma unroll
      for(int nd=0;nd<4;nd++){
        const uint32_t r=ki*16+(lane&15);
        const uint32_t chk=nd*2+(lane>>4);
        uint32_t vh[4];
        ldsm4t(vh, st+8192+soff(r,chk));
        #pragma unroll
        for(int mi=0;mi<2;mi++){
          mmah(O[mi][2*nd],   p[mi], vh[0], vh[1]);
          mmah(O[mi][2*nd+1], p[mi], vh[2], vh[3]);
        }
      }
    }
    __syncthreads();
    if(t+2<NT){ attn_loadkv(KV,sb,tid,(size_t)b*KL+(size_t)(t+2)*64,h,t&1); CP_COMMIT(); }
  }

  #pragma unroll
  for(int mi=0;mi<2;mi++)
    #pragma unroll
    for(int hh=0;hh<2;hh++){
      const float inv=1.f/lrun[mi][hh];
      const size_t grow=qrow0+wid*32+mi*16+(lane>>2)+hh*8;
      #pragma unroll
      for(int nj=0;nj<8;nj++){
        const int gcol=h*64+nj*8+2*(lane&3);
        *(uint32_t*)(C+grow*DIM+gcol)=packh(O[mi][nj][2*hh]*inv, O[mi][nj][2*hh+1]*inv);
      }
    }
}

// ---------------- launch ----------------
extern "C" void kernel_launch(void* const* d_in, const int* in_sizes, int n_in,
                              void* d_out, int out_size){
  const float* q   =(const float*)d_in[0];
  const float* kv  =(const float*)d_in[1];
  const int*   ids =(const int*)  d_in[3];
  const float* ln1s=(const float*)d_in[4];
  const float* ln1b=(const float*)d_in[5];
  const float* Wq  =(const float*)d_in[6];
  const float* Wkv =(const float*)d_in[7];
  const float* Wo  =(const float*)d_in[8];
  const float* ln2s=(const float*)d_in[9];
  const float* ln2b=(const float*)d_in[10];
  const float* W1  =(const float*)d_in[11];
  const float* W2  =(const float*)d_in[12];
  const float* pe  =(const float*)d_in[13];
  float* out=(float*)d_out;

#define SYM(v,s) void* v##_; cudaGetSymbolAddress(&v##_,s);
  SYM(wq,w_q) SYM(wkv,w_kv) SYM(wo,w_o) SYM(w1,w_1) SYM(w2,w_2)
  SYM(qln,g_qln) SYM(kpe,g_kvpe) SYM(qp,g_qp) SYM(kvp,g_kvp)
  SYM(ctx,g_ctx) SYM(atf,g_attn) SYM(hbuf,g_hb) SYM(inbuf,g_in)
#undef SYM
#define HF(p) ((__half*)p##_)
#define FL(p) ((float*)p##_)

  cudaFuncSetAttribute(mm1_kernel<0>, cudaFuncAttributeMaxDynamicSharedMemorySize, MM1_SMEM);
  cudaFuncSetAttribute(mm1_kernel<1>, cudaFuncAttributeMaxDynamicSharedMemorySize, MM1_SMEM);
  cudaFuncSetAttribute(mm1_kernel<2>, cudaFuncAttributeMaxDynamicSharedMemorySize, MM1_SMEM);
  cudaFuncSetAttribute(mm1_kernel<4>, cudaFuncAttributeMaxDynamicSharedMemorySize, MM1_SMEM);
  cudaFuncSetAttribute(attn_kernel,   cudaFuncAttributeMaxDynamicSharedMemorySize, AT_SMEM);

  dim3 tb(32,8);
  // ncu captures launch #4 -> keep the biggest GEMM (kv-proj) there
  tsplit1_kernel<<<dim3(2*DIM/32,DIM/32),tb>>>(Wkv, HF(wkv), DIM, 2*DIM);            // 1
  kvpe_half_kernel<<<MKV,256>>>(kv, pe, ids, HF(kpe));                               // 2
  tsplit1_kernel<<<dim3(DIM/32,DIM/32),tb>>>(Wq, HF(wq), DIM, DIM);                  // 3
  mm1_kernel<4><<<dim3(2*DIM/128,MKV/128),256,MM1_SMEM>>>(HF(kpe),HF(wkv),
      nullptr,nullptr,HF(kvp),2*DIM,DIM);                                            // 4 (ncu)
  ln_half_kernel<<<MQ,256>>>(q, ln1s, ln1b, HF(qln));                                // 5
  mm1_kernel<2><<<dim3(DIM/128,MQ/128),256,MM1_SMEM>>>(HF(qln),HF(wq),
      nullptr,nullptr,HF(qp),DIM,DIM);                                               // 6
  tsplit1_kernel<<<dim3(DIM/32,DIM/32),tb>>>(Wo, HF(wo), DIM, DIM);                  // 7
  tsplit1_kernel<<<dim3(INNER/32,DIM/32),tb>>>(W1, HF(w1), DIM, INNER);              // 8
  tsplit1_kernel<<<dim3(DIM/32,INNER/32),tb>>>(W2, HF(w2), INNER, DIM);              // 9

  attn_kernel<<<dim3(QL/128,HEADS,BATCH),128,AT_SMEM>>>(HF(qp),HF(kvp),HF(ctx));     // 10

  mm1_kernel<1><<<dim3(DIM/128,MQ/128),256,MM1_SMEM>>>(HF(ctx),HF(wo),
      q,FL(atf),nullptr,DIM,DIM);                                                    // 11
  ln_half_kernel<<<MQ,256>>>(FL(atf), ln2s, ln2b, HF(hbuf));                         // 12
  mm1_kernel<0><<<dim3(INNER/128,MQ/128),256,MM1_SMEM>>>(HF(hbuf),HF(w1),
      nullptr,nullptr,HF(inbuf),INNER,DIM);                                          // 13
  mm1_kernel<1><<<dim3(DIM/128,MQ/128),256,MM1_SMEM>>>(HF(inbuf),HF(w2),
      FL(atf),out,nullptr,DIM,INNER);                                                // 14
}